// round 14
// baseline (speedup 1.0000x reference)
#include <cuda_runtime.h>
#include <cuda_fp16.h>
#include <cstdint>

#define Bc   4
#define Sc   1024
#define Dc   1024
#define Hc   16
#define DHc  64
#define DFFc 4096
#define DLATc 256
#define Mrows (Bc * Sc)   // 4096

// ---------------- scratch (no cudaMalloc allowed) ----------------
__device__ float  g_F  [Bc * Sc * Dc];
__device__ float  g_ZW1[Bc * DFFc];
__device__ __half g_Oh [Mrows * Dc];
__device__ __half g_Qh [Mrows * Dc];
__device__ __half g_Kh [Mrows * Dc];
__device__ __half g_Vh [Mrows * Dc];
__device__ __half g_xh [Mrows * Dc];
__device__ __half g_O2h[Mrows * Dc];
__device__ __half g_Hh [Mrows * DFFc];
__device__ __half g_WQh[Dc * Dc];
__device__ __half g_WKh[Dc * Dc];
__device__ __half g_WVh[Dc * Dc];
__device__ __half g_W1h[Dc * DFFc];     // first 1024 rows of W1 only
__device__ __half g_W2h[DFFc * Dc];

// ---------------- PTX helpers (base ISA only) ----------------
__device__ __forceinline__ void mma_f16_16x8x16(
    float& c0, float& c1, float& c2, float& c3,
    uint32_t a0, uint32_t a1, uint32_t a2, uint32_t a3,
    uint32_t b0, uint32_t b1)
{
    asm("mma.sync.aligned.m16n8k16.row.col.f32.f16.f16.f32 "
        "{%0,%1,%2,%3}, {%4,%5,%6,%7}, {%8,%9}, {%0,%1,%2,%3};"
        : "+f"(c0), "+f"(c1), "+f"(c2), "+f"(c3)
        : "r"(a0), "r"(a1), "r"(a2), "r"(a3), "r"(b0), "r"(b1));
}
#define LDSM_X4(r0, r1, r2, r3, addr) \
    asm volatile("ldmatrix.sync.aligned.m8n8.x4.shared.b16 {%0,%1,%2,%3}, [%4];" \
        : "=r"(r0), "=r"(r1), "=r"(r2), "=r"(r3) : "r"(addr))
#define LDSM_X4T(r0, r1, r2, r3, addr) \
    asm volatile("ldmatrix.sync.aligned.m8n8.x4.trans.shared.b16 {%0,%1,%2,%3}, [%4];" \
        : "=r"(r0), "=r"(r1), "=r"(r2), "=r"(r3) : "r"(addr))
#define LDSM_X2(r0, r1, addr) \
    asm volatile("ldmatrix.sync.aligned.m8n8.x2.shared.b16 {%0,%1}, [%2];" \
        : "=r"(r0), "=r"(r1) : "r"(addr))
#define LDSM_X2T(r0, r1, addr) \
    asm volatile("ldmatrix.sync.aligned.m8n8.x2.trans.shared.b16 {%0,%1}, [%2];" \
        : "=r"(r0), "=r"(r1) : "r"(addr))
__device__ __forceinline__ uint32_t smem_to_u32(const void* p) {
    uint32_t a;
    asm("{ .reg .u64 t; cvta.to.shared.u64 t, %1; cvt.u32.u64 %0, t; }" : "=r"(a) : "l"(p));
    return a;
}
__device__ __forceinline__ uint32_t hmul2b(uint32_t a, uint32_t b) {
    __half2 r = __hmul2(*(__half2*)&a, *(__half2*)&b);
    return *(uint32_t*)&r;
}
__device__ __forceinline__ uint32_t pack_h2(float a, float b) {
    __half2 h = __floats2half2_rn(a, b);
    return *(uint32_t*)&h;
}
#define CP_ASYNC16(dst, src) \
    asm volatile("cp.async.cg.shared.global [%0], [%1], 16;" :: "r"(dst), "l"(src))
#define CP_COMMIT() asm volatile("cp.async.commit_group;" ::: "memory")
#define CP_WAIT1()  asm volatile("cp.async.wait_group 1;" ::: "memory")
#define CP_WAIT0()  asm volatile("cp.async.wait_group 0;" ::: "memory")

// ---------------- fused prep: all fp16 conversions + zw1 ----------------
#define PREP_CVT_BLOCKS 7680
#define PREP_BLOCKS (PREP_CVT_BLOCKS + 16)
__global__ void __launch_bounds__(256) prep_kernel(
    const float* __restrict__ x,  const float* __restrict__ WQ,
    const float* __restrict__ WK, const float* __restrict__ WV,
    const float* __restrict__ W1, const float* __restrict__ W2,
    const float* __restrict__ z,
    __half* __restrict__ xh,  __half* __restrict__ WQh,
    __half* __restrict__ WKh, __half* __restrict__ WVh,
    __half* __restrict__ W1h, __half* __restrict__ W2h,
    float* __restrict__ zw1)
{
    const int bid = blockIdx.x;
    if (bid < PREP_CVT_BLOCKS) {
        int g = bid * 256 + threadIdx.x;         // 8-elem group index
        const float* s; __half* d;
        if      (g < 524288)  { s = x;  d = xh;  }
        else if (g < 655360)  { s = WQ; d = WQh; g -= 524288; }
        else if (g < 786432)  { s = WK; d = WKh; g -= 655360; }
        else if (g < 917504)  { s = WV; d = WVh; g -= 786432; }
        else if (g < 1441792) { s = W1; d = W1h; g -= 917504; }
        else                  { s = W2; d = W2h; g -= 1441792; }
        const int i = g * 8;
        float4 v0 = *(const float4*)(s + i);
        float4 v1 = *(const float4*)(s + i + 4);
        __half2 h0 = __floats2half2_rn(v0.x, v0.y);
        __half2 h1 = __floats2half2_rn(v0.z, v0.w);
        __half2 h2 = __floats2half2_rn(v1.x, v1.y);
        __half2 h3 = __floats2half2_rn(v1.z, v1.w);
        *(uint4*)(d + i) = make_uint4(*(uint32_t*)&h0, *(uint32_t*)&h1,
                                      *(uint32_t*)&h2, *(uint32_t*)&h3);
    } else {
        const int n = (bid - PREP_CVT_BLOCKS) * 256 + threadIdx.x;  // 0..4095
        float a0 = 0.f, a1 = 0.f, a2 = 0.f, a3 = 0.f;
#pragma unroll 8
        for (int k = 0; k < DLATc; k++) {
            const float w = W1[(size_t)(Dc + k) * DFFc + n];
            a0 += z[k] * w;
            a1 += z[DLATc + k] * w;
            a2 += z[2 * DLATc + k] * w;
            a3 += z[3 * DLATc + k] * w;
        }
        zw1[n] = a0;
        zw1[DFFc + n] = a1;
        zw1[2 * DFFc + n] = a2;
        zw1[3 * DFFc + n] = a3;
    }
}

// ---------------- fp16 mma.sync GEMM (unchanged core from R13) ----------------
#define AROW_B 144
#define BROW_B 272
#define A_BYTES (128 * AROW_B)
#define B_BYTES (64 * BROW_B)
#define BUF_BYTES (A_BYTES + B_BYTES)
#define GEMM_SMEM_BYTES (2 * BUF_BYTES)   // 71680

template<int OUTHALF>
__device__ __forceinline__ void gemm_body(
    char* smem, const __half* __restrict__ A,
    const __half* __restrict__ W, const float* __restrict__ bias,
    const float* __restrict__ zbias,
    void* __restrict__ Cv, int N, int K, int relu, int row0, int col0)
{
    const uint32_t sb = smem_to_u32(smem);
    const int tid  = threadIdx.x;
    const int wid  = tid >> 5, lane = tid & 31;
    const int wm   = wid >> 2, wn = wid & 3;
    const int qrow = lane >> 2, qcol = lane & 3;
    const int l16  = lane & 15, lhi = lane >> 4;
    const int mgrp = lane >> 3;

    float acc[4][4][4];
#pragma unroll
    for (int i = 0; i < 4; i++)
#pragma unroll
        for (int j = 0; j < 4; j++)
#pragma unroll
            for (int r = 0; r < 4; r++) acc[i][j][r] = 0.f;

    const int NC = K / 64;

#define LOAD_CHUNK(c, s) do {                                                        \
    const int _k0 = (c) * 64;                                                        \
    const uint32_t _ab = sb + (uint32_t)((s) * BUF_BYTES);                           \
    const uint32_t _bb = _ab + A_BYTES;                                              \
    _Pragma("unroll")                                                                \
    for (int _u = tid; _u < 1024; _u += 256) {                                       \
        {                                                                            \
            const int _r = _u >> 3, _sg = _u & 7;                                    \
            const __half* _as = A + (size_t)(row0 + _r) * K + _k0 + _sg * 8;         \
            CP_ASYNC16(_ab + (uint32_t)(_r * AROW_B + _sg * 16), _as);               \
        }                                                                            \
        {                                                                            \
            const int _r = _u >> 4, _sg = _u & 15;                                   \
            const __half* _bs = W + (size_t)(_k0 + _r) * N + col0 + _sg * 8;         \
            CP_ASYNC16(_bb + (uint32_t)(_r * BROW_B + _sg * 16), _bs);               \
        }                                                                            \
    }                                                                                \
    CP_COMMIT();                                                                     \
} while (0)

    LOAD_CHUNK(0, 0);
    for (int c = 0; c < NC; c++) {
        const int s = c & 1;
        if (c + 1 < NC) { LOAD_CHUNK(c + 1, s ^ 1); CP_WAIT1(); }
        else            { CP_WAIT0(); }
        __syncthreads();

        const uint32_t ab = sb + (uint32_t)(s * BUF_BYTES);
        const uint32_t bb = ab + A_BYTES;
#pragma unroll
        for (int ks = 0; ks < 4; ks++) {
            const int k = ks * 16;
            uint32_t af[4][4];
#pragma unroll
            for (int mt = 0; mt < 4; mt++) {
                const uint32_t addr = ab
                    + (uint32_t)((wm * 64 + mt * 16 + l16) * AROW_B)
                    + (uint32_t)((k + lhi * 8) * 2);
                LDSM_X4(af[mt][0], af[mt][1], af[mt][2], af[mt][3], addr);
            }
            uint32_t bf[4][2];
#pragma unroll
            for (int ntp = 0; ntp < 2; ntp++) {
                const int row = k + (lane & 7) + (mgrp & 1) * 8;
                const int col = wn * 32 + ntp * 16 + (mgrp >> 1) * 8;
                const uint32_t addr = bb + (uint32_t)(row * BROW_B + col * 2);
                LDSM_X4T(bf[2 * ntp][0], bf[2 * ntp][1],
                         bf[2 * ntp + 1][0], bf[2 * ntp + 1][1], addr);
            }
#pragma unroll
            for (int mt = 0; mt < 4; mt++)
#pragma unroll
                for (int nt = 0; nt < 4; nt++)
                    mma_f16_16x8x16(acc[mt][nt][0], acc[mt][nt][1],
                                    acc[mt][nt][2], acc[mt][nt][3],
                                    af[mt][0], af[mt][1], af[mt][2], af[mt][3],
                                    bf[nt][0], bf[nt][1]);
        }
        __syncthreads();
    }

    const float* zb = zbias ? (zbias + (size_t)(row0 >> 10) * N) : nullptr;
#pragma unroll
    for (int mt = 0; mt < 4; mt++) {
        const int r = row0 + wm * 64 + mt * 16 + qrow;
#pragma unroll
        for (int nt = 0; nt < 4; nt++) {
            const int cc = col0 + wn * 32 + nt * 8 + 2 * qcol;
            float2 v0, v1;
            v0.x = acc[mt][nt][0]; v0.y = acc[mt][nt][1];
            v1.x = acc[mt][nt][2]; v1.y = acc[mt][nt][3];
            if (bias) {
                float bx = bias[cc], by = bias[cc + 1];
                if (zb) { bx += zb[cc]; by += zb[cc + 1]; }
                v0.x += bx; v0.y += by; v1.x += bx; v1.y += by;
            }
            if (relu) {
                v0.x = fmaxf(v0.x, 0.f); v0.y = fmaxf(v0.y, 0.f);
                v1.x = fmaxf(v1.x, 0.f); v1.y = fmaxf(v1.y, 0.f);
            }
            if (OUTHALF) {
                __half* Ch = (__half*)Cv;
                __half2 h0 = __floats2half2_rn(v0.x, v0.y);
                __half2 h1 = __floats2half2_rn(v1.x, v1.y);
                *(__half2*)(Ch + (size_t)r * N + cc)       = h0;
                *(__half2*)(Ch + (size_t)(r + 8) * N + cc) = h1;
            } else {
                float* C = (float*)Cv;
                *(float2*)(C + (size_t)r * N + cc)       = v0;
                *(float2*)(C + (size_t)(r + 8) * N + cc) = v1;
            }
        }
    }
#undef LOAD_CHUNK
}

template<int OUTHALF>
__global__ void __launch_bounds__(256, 2) mma_gemm(
    const __half* __restrict__ A, const __half* __restrict__ W,
    const float* __restrict__ bias, const float* __restrict__ zbias,
    void* __restrict__ C, int N, int K, int relu)
{
    extern __shared__ char smem[];
    gemm_body<OUTHALF>(smem, A, W, bias, zbias, C, N, K, relu,
                       blockIdx.y * 128, blockIdx.x * 128);
}

__global__ void __launch_bounds__(256, 2) qkv_gemm(
    const __half* __restrict__ xh,
    const __half* __restrict__ WQ, const __half* __restrict__ WK,
    const __half* __restrict__ WV,
    __half* __restrict__ Q, __half* __restrict__ K, __half* __restrict__ V)
{
    extern __shared__ char smem[];
    const int sel  = blockIdx.x >> 3;
    const int col0 = (blockIdx.x & 7) << 7;
    const __half* W = (sel == 0) ? WQ : (sel == 1) ? WK : WV;
    __half*       C = (sel == 0) ? Q  : (sel == 1) ? K  : V;
    gemm_body<1>(smem, xh, W, nullptr, nullptr, C, Dc, Dc, 0,
                 blockIdx.y * 128, col0);
}

// ---------------- fp16 flash attention (+ diagonal-tile MMA skipping) -------
#define KROW 72
__global__ void __launch_bounds__(128, 4) attn_kernel(
    const __half* __restrict__ Q, const __half* __restrict__ K,
    const __half* __restrict__ V, const int* __restrict__ mask,
    __half* __restrict__ O)
{
    __shared__ __half Ks[64 * KROW];
    __shared__ __half Vs[64 * KROW];
    __shared__ int    km[64];
    const int qt = gridDim.x - 1 - blockIdx.x;   // LPT: longest first
    const int h = blockIdx.y, b = blockIdx.z;
    const int q0 = qt * 64;
    const int tid = threadIdx.x;
    const int w = tid >> 5, lane = tid & 31;
    const int qrow = lane >> 2, qcol = lane & 3;
    const int l16 = lane & 15, lhi = lane >> 4;
    const size_t base = ((size_t)b * Sc) * Dc + (size_t)h * DHc;
    const uint32_t ksb = smem_to_u32(Ks);
    const uint32_t vsb = smem_to_u32(Vs);

    for (int i = tid; i < 64 * 8; i += 128) {
        const int r = i >> 3, c = (i & 7) * 8;
        *(uint4*)(Ks + r * KROW + c) =
            *(const uint4*)(Q + base + (size_t)(q0 + r) * Dc + c);
    }
    __syncthreads();
    uint32_t qf[4][4];
    {
        const uint32_t s2 = 0x30003000u;   // half2(0.125, 0.125)
#pragma unroll
        for (int ks = 0; ks < 4; ks++) {
            const uint32_t addr = ksb
                + (uint32_t)(((w * 16 + l16) * KROW + ks * 16 + lhi * 8) * 2);
            LDSM_X4(qf[ks][0], qf[ks][1], qf[ks][2], qf[ks][3], addr);
            qf[ks][0] = hmul2b(qf[ks][0], s2);
            qf[ks][1] = hmul2b(qf[ks][1], s2);
            qf[ks][2] = hmul2b(qf[ks][2], s2);
            qf[ks][3] = hmul2b(qf[ks][3], s2);
        }
    }
    const int qg0 = q0 + w * 16 + qrow, qg1 = qg0 + 8;
    const int mq0 = mask[b * Sc + qg0], mq1 = mask[b * Sc + qg1];

    float m0 = -1e30f, m1 = -1e30f, l0 = 0.f, l1 = 0.f;
    float oacc[8][4];
#pragma unroll
    for (int nt = 0; nt < 8; nt++)
#pragma unroll
        for (int e = 0; e < 4; e++) oacc[nt][e] = 0.f;

    for (int kt = 0; kt <= qt; kt++) {
        const int k0 = kt * 64;
        // diag tile: warp w's queries end at w*16+15 -> key-groups beyond are
        // fully causal-masked; skip their QK MMAs (nt>=2w+2) and PV (ks>w).
        const int ntmax = (kt == qt) ? (2 * w + 2) : 8;
        const int ksmax = (kt == qt) ? (w + 1) : 4;
        __syncthreads();
        for (int i = tid; i < 64 * 8; i += 128) {
            const int r = i >> 3, c = (i & 7) * 8;
            *(uint4*)(Ks + r * KROW + c) =
                *(const uint4*)(K + base + (size_t)(k0 + r) * Dc + c);
            *(uint4*)(Vs + r * KROW + c) =
                *(const uint4*)(V + base + (size_t)(k0 + r) * Dc + c);
        }
        if (tid < 64) km[tid] = mask[b * Sc + k0 + tid];
        __syncthreads();

        float sc[8][4];
#pragma unroll
        for (int nt = 0; nt < 8; nt++) {
            sc[nt][0] = sc[nt][1] = sc[nt][2] = sc[nt][3] = 0.f;
            if (nt >= ntmax) continue;
#pragma unroll
            for (int ks = 0; ks < 4; ks++) {
                uint32_t b0, b1;
                const uint32_t addr = ksb
                    + (uint32_t)(((nt * 8 + (l16 & 7)) * KROW
                                  + ks * 16 + (l16 >> 3) * 8) * 2);
                LDSM_X2(b0, b1, addr);
                mma_f16_16x8x16(sc[nt][0], sc[nt][1], sc[nt][2], sc[nt][3],
                                qf[ks][0], qf[ks][1], qf[ks][2], qf[ks][3], b0, b1);
            }
        }
        float mt0 = -1e30f, mt1 = -1e30f;
#pragma unroll
        for (int nt = 0; nt < 8; nt++) {
            const int kk0 = nt * 8 + 2 * qcol, kk1 = kk0 + 1;
            const int msk0 = km[kk0], msk1 = km[kk1];
            if ((k0 + kk0) > qg0 || msk0 == 0) sc[nt][0] = -1e30f;
            if ((k0 + kk1) > qg0 || msk1 == 0) sc[nt][1] = -1e30f;
            if ((k0 + kk0) > qg1 || msk0 == 0) sc[nt][2] = -1e30f;
            if ((k0 + kk1) > qg1 || msk1 == 0) sc[nt][3] = -1e30f;
            mt0 = fmaxf(mt0, fmaxf(sc[nt][0], sc[nt][1]));
            mt1 = fmaxf(mt1, fmaxf(sc[nt][2], sc[nt][3]));
        }
        mt0 = fmaxf(mt0, __shfl_xor_sync(0xffffffffu, mt0, 1));
        mt0 = fmaxf(mt0, __shfl_xor_sync(0xffffffffu, mt0, 2));
        mt1 = fmaxf(mt1, __shfl_xor_sync(0xffffffffu, mt1, 1));
        mt1 = fmaxf(mt1, __shfl_xor_sync(0xffffffffu, mt1, 2));
        const float mn0 = fmaxf(m0, mt0), mn1 = fmaxf(m1, mt1);
        const float sc0 = __expf(m0 - mn0), sc1 = __expf(m1 - mn1);
        float lt0 = 0.f, lt1 = 0.f;
#pragma unroll
        for (int nt = 0; nt < 8; nt++) {
            sc[nt][0] = __expf(sc[nt][0] - mn0);
            sc[nt][1] = __expf(sc[nt][1] - mn0);
            sc[nt][2] = __expf(sc[nt][2] - mn1);
            sc[nt][3] = __expf(sc[nt][3] - mn1);
            lt0 += sc[nt][0] + sc[nt][1];
            lt1 += sc[nt][2] + sc[nt][3];
        }
        lt0 += __shfl_xor_sync(0xffffffffu, lt0, 1);
        lt0 += __shfl_xor_sync(0xffffffffu, lt0, 2);
        lt1 += __shfl_xor_sync(0xffffffffu, lt1, 1);
        lt1 += __shfl_xor_sync(0xffffffffu, lt1, 2);
        l0 = l0 * sc0 + lt0; m0 = mn0;
        l1 = l1 * sc1 + lt1; m1 = mn1;
#pragma unroll
        for (int nt = 0; nt < 8; nt++) {
            oacc[nt][0] *= sc0; oacc[nt][1] *= sc0;
            oacc[nt][2] *= sc1; oacc[nt][3] *= sc1;
        }

        uint32_t pf[4][4];
#pragma unroll
        for (int ks = 0; ks < 4; ks++) {
            pf[ks][0] = pack_h2(sc[2 * ks][0],     sc[2 * ks][1]);
            pf[ks][1] = pack_h2(sc[2 * ks][2],     sc[2 * ks][3]);
            pf[ks][2] = pack_h2(sc[2 * ks + 1][0], sc[2 * ks + 1][1]);
            pf[ks][3] = pack_h2(sc[2 * ks + 1][2], sc[2 * ks + 1][3]);
        }
#pragma unroll
        for (int nt = 0; nt < 8; nt++) {
#pragma unroll
            for (int ks = 0; ks < 4; ks++) {
                if (ks >= ksmax) break;   // p == 0 for skipped key groups
                uint32_t b0, b1;
                const uint32_t addr = vsb
                    + (uint32_t)(((ks * 16 + l16) * KROW + nt * 8) * 2);
                LDSM_X2T(b0, b1, addr);
                mma_f16_16x8x16(oacc[nt][0], oacc[nt][1], oacc[nt][2], oacc[nt][3],
                                pf[ks][0], pf[ks][1], pf[ks][2], pf[ks][3], b0, b1);
            }
        }
    }

    const float inv0 = (mq0 != 0) ? (1.0f / l0) : 0.f;
    const float inv1 = (mq1 != 0) ? (1.0f / l1) : 0.f;
    __half* o0 = O + base + (size_t)qg0 * Dc;
    __half* o1 = O + base + (size_t)qg1 * Dc;
#pragma unroll
    for (int nt = 0; nt < 8; nt++) {
        const int cc = nt * 8 + 2 * qcol;
        __half2 h0 = __floats2half2_rn(oacc[nt][0] * inv0, oacc[nt][1] * inv0);
        __half2 h1 = __floats2half2_rn(oacc[nt][2] * inv1, oacc[nt][3] * inv1);
        *(__half2*)(o0 + cc) = h0;
        *(__half2*)(o1 + cc) = h1;
    }
}

// ---------------- layernorm (vectorized: thread owns 4 contiguous elems) ----
__device__ __forceinline__ float block_sum(float v, float* red) {
#pragma unroll
    for (int o = 16; o > 0; o >>= 1) v += __shfl_xor_sync(0xffffffffu, v, o);
    const int lane = threadIdx.x & 31, w = threadIdx.x >> 5;
    __syncthreads();
    if (lane == 0) red[w] = v;
    __syncthreads();
    float s = 0.f;
#pragma unroll
    for (int i = 0; i < 8; i++) s += red[i];
    return s;
}

// out2h = fp16( LN2(LN1(x+o)+cond) )  — fp32 out2 dropped entirely
__global__ void __launch_bounds__(256) ln12_kernel(
    const float* __restrict__ x, const __half* __restrict__ o,
    const float* __restrict__ cond,
    const float* __restrict__ g1, const float* __restrict__ b1,
    const float* __restrict__ g2, const float* __restrict__ b2,
    __half* __restrict__ out2h)
{
    __shared__ float red[8];
    const int row = blockIdx.x;
    const int bb  = row >> 10;
    const int d0  = threadIdx.x * 4;
    float t[4];
    {
        float4 xv = *(const float4*)(x + (size_t)row * Dc + d0);
        uint2  ov = *(const uint2*)(o + (size_t)row * Dc + d0);
        float2 o0 = __half22float2(*(__half2*)&ov.x);
        float2 o1 = __half22float2(*(__half2*)&ov.y);
        t[0] = xv.x + o0.x; t[1] = xv.y + o0.y;
        t[2] = xv.z + o1.x; t[3] = xv.w + o1.y;
    }
    float s = t[0] + t[1] + t[2] + t[3];
    float mu = block_sum(s, red) * (1.f / 1024.f);
    float vs = 0.f;
#pragma unroll
    for (int k = 0; k < 4; k++) { float dv = t[k] - mu; vs += dv * dv; }
    float var = block_sum(vs, red) * (1.f / 1024.f);
    float inv = rsqrtf(var + 1e-3f);
    {
        float4 gv = *(const float4*)(g1 + d0);
        float4 bv = *(const float4*)(b1 + d0);
        float4 cv = *(const float4*)(cond + (size_t)bb * Dc + d0);
        t[0] = (t[0] - mu) * inv * gv.x + bv.x + cv.x;
        t[1] = (t[1] - mu) * inv * gv.y + bv.y + cv.y;
        t[2] = (t[2] - mu) * inv * gv.z + bv.z + cv.z;
        t[3] = (t[3] - mu) * inv * gv.w + bv.w + cv.w;
    }
    s = t[0] + t[1] + t[2] + t[3];
    mu = block_sum(s, red) * (1.f / 1024.f);
    vs = 0.f;
#pragma unroll
    for (int k = 0; k < 4; k++) { float dv = t[k] - mu; vs += dv * dv; }
    var = block_sum(vs, red) * (1.f / 1024.f);
    inv = rsqrtf(var + 1e-3f);
    {
        float4 gv = *(const float4*)(g2 + d0);
        float4 bv = *(const float4*)(b2 + d0);
        float y0 = (t[0] - mu) * inv * gv.x + bv.x;
        float y1 = (t[1] - mu) * inv * gv.y + bv.y;
        float y2 = (t[2] - mu) * inv * gv.z + bv.z;
        float y3 = (t[3] - mu) * inv * gv.w + bv.w;
        __half2 h0 = __floats2half2_rn(y0, y1);
        __half2 h1 = __floats2half2_rn(y2, y3);
        *(uint2*)(out2h + (size_t)row * Dc + d0) =
            make_uint2(*(uint32_t*)&h0, *(uint32_t*)&h1);
    }
}

// out = LN3(out2h + f)   (a in fp16, f in fp32)
__global__ void __launch_bounds__(256) ln3_kernel(
    const __half* __restrict__ a, const float* __restrict__ f,
    const float* __restrict__ g3, const float* __restrict__ b3,
    float* __restrict__ out)
{
    __shared__ float red[8];
    const int row = blockIdx.x;
    const int d0  = threadIdx.x * 4;
    float t[4];
    {
        uint2  av = *(const uint2*)(a + (size_t)row * Dc + d0);
        float4 fv = *(const float4*)(f + (size_t)row * Dc + d0);
        float2 a0 = __half22float2(*(__half2*)&av.x);
        float2 a1 = __half22float2(*(__half2*)&av.y);
        t[0] = a0.x + fv.x; t[1] = a0.y + fv.y;
        t[2] = a1.x + fv.z; t[3] = a1.y + fv.w;
    }
    float s = t[0] + t[1] + t[2] + t[3];
    float mu = block_sum(s, red) * (1.f / 1024.f);
    float vs = 0.f;
#pragma unroll
    for (int k = 0; k < 4; k++) { float dv = t[k] - mu; vs += dv * dv; }
    float var = block_sum(vs, red) * (1.f / 1024.f);
    float inv = rsqrtf(var + 1e-3f);
    {
        float4 gv = *(const float4*)(g3 + d0);
        float4 bv = *(const float4*)(b3 + d0);
        float4 ov;
        ov.x = (t[0] - mu) * inv * gv.x + bv.x;
        ov.y = (t[1] - mu) * inv * gv.y + bv.y;
        ov.z = (t[2] - mu) * inv * gv.z + bv.z;
        ov.w = (t[3] - mu) * inv * gv.w + bv.w;
        *(float4*)(out + (size_t)row * Dc + d0) = ov;
    }
}

// ---------------- launch ----------------
extern "C" void kernel_launch(void* const* d_in, const int* in_sizes, int n_in,
                              void* d_out, int out_size) {
    const float* x    = (const float*)d_in[0];
    const float* z    = (const float*)d_in[1];
    const float* cond = (const float*)d_in[2];
    const int*   xm   = (const int*)  d_in[3];
    const float* WQ   = (const float*)d_in[4];
    const float* WK   = (const float*)d_in[5];
    const float* WV   = (const float*)d_in[6];
    const float* W1   = (const float*)d_in[7];
    const float* b1   = (const float*)d_in[8];
    const float* W2   = (const float*)d_in[9];
    const float* b2   = (const float*)d_in[10];
    const float* g1   = (const float*)d_in[11];
    const float* be1  = (const float*)d_in[12];
    const float* g2   = (const float*)d_in[13];
    const float* be2  = (const float*)d_in[14];
    const float* g3   = (const float*)d_in[15];
    const float* be3  = (const float*)d_in[16];
    float* out = (float*)d_out;

    float *pF, *pZW1;
    __half *pOh, *pQh, *pKh, *pVh, *pxh, *pO2h, *pHh, *pWQh, *pWKh, *pWVh, *pW1h, *pW2h;
    cudaGetSymbolAddress((void**)&pF,   g_F);
    cudaGetSymbolAddress((void**)&pZW1, g_ZW1);
    cudaGetSymbolAddress((void**)&pOh,  g_Oh);
    cudaGetSymbolAddress((void**)&pQh,  g_Qh);
    cudaGetSymbolAddress((void**)&pKh,  g_Kh);
    cudaGetSymbolAddress((void**)&pVh,  g_Vh);
    cudaGetSymbolAddress((void**)&pxh,  g_xh);
    cudaGetSymbolAddress((void**)&pO2h, g_O2h);
    cudaGetSymbolAddress((void**)&pHh,  g_Hh);
    cudaGetSymbolAddress((void**)&pWQh, g_WQh);
    cudaGetSymbolAddress((void**)&pWKh, g_WKh);
    cudaGetSymbolAddress((void**)&pWVh, g_WVh);
    cudaGetSymbolAddress((void**)&pW1h, g_W1h);
    cudaGetSymbolAddress((void**)&pW2h, g_W2h);

    cudaFuncSetAttribute(mma_gemm<0>, cudaFuncAttributeMaxDynamicSharedMemorySize,
                         GEMM_SMEM_BYTES);
    cudaFuncSetAttribute(mma_gemm<1>, cudaFuncAttributeMaxDynamicSharedMemorySize,
                         GEMM_SMEM_BYTES);
    cudaFuncSetAttribute(qkv_gemm, cudaFuncAttributeMaxDynamicSharedMemorySize,
                         GEMM_SMEM_BYTES);

    prep_kernel<<<PREP_BLOCKS, 256>>>(x, WQ, WK, WV, W1, W2, z,
                                      pxh, pWQh, pWKh, pWVh, pW1h, pW2h, pZW1);

    qkv_gemm<<<dim3(24, Mrows / 128), 256, GEMM_SMEM_BYTES>>>(
        pxh, pWQh, pWKh, pWVh, pQh, pKh, pVh);

    attn_kernel<<<dim3(Sc / 64, Hc, Bc), 128>>>(pQh, pKh, pVh, xm, pOh);

    ln12_kernel<<<Mrows, 256>>>(x, pOh, cond, g1, be1, g2, be2, pO2h);

    mma_gemm<1><<<dim3(DFFc / 128, Mrows / 128), 256, GEMM_SMEM_BYTES>>>(
        pO2h, pW1h, b1, pZW1, pHh, DFFc, Dc, 1);
    mma_gemm<0><<<dim3(Dc / 128, Mrows / 128), 256, GEMM_SMEM_BYTES>>>(
        pHh, pW2h, b2, nullptr, pF, Dc, DFFc, 0);

    ln3_kernel<<<Mrows, 256>>>(pO2h, pF, g3, be3, out);
}

// round 15
// speedup vs baseline: 1.0508x; 1.0508x over previous
#include <cuda_runtime.h>
#include <cuda_fp16.h>
#include <cstdint>

#define Bc   4
#define Sc   1024
#define Dc   1024
#define Hc   16
#define DHc  64
#define DFFc 4096
#define DLATc 256
#define Mrows (Bc * Sc)   // 4096

// ---------------- scratch (no cudaMalloc allowed) ----------------
__device__ float  g_F  [Bc * Sc * Dc];
__device__ float  g_ZW1[Bc * DFFc];
__device__ __half g_Oh [Mrows * Dc];
__device__ __half g_Qh [Mrows * Dc];
__device__ __half g_Kh [Mrows * Dc];
__device__ __half g_Vh [Mrows * Dc];
__device__ __half g_xh [Mrows * Dc];
__device__ __half g_O2h[Mrows * Dc];
__device__ __half g_Hh [Mrows * DFFc];
__device__ __half g_WQh[Dc * Dc];
__device__ __half g_WKh[Dc * Dc];
__device__ __half g_WVh[Dc * Dc];
__device__ __half g_W1h[Dc * DFFc];     // first 1024 rows of W1 only
__device__ __half g_W2h[DFFc * Dc];

// ---------------- PTX helpers (base ISA only) ----------------
__device__ __forceinline__ void mma_f16_16x8x16(
    float& c0, float& c1, float& c2, float& c3,
    uint32_t a0, uint32_t a1, uint32_t a2, uint32_t a3,
    uint32_t b0, uint32_t b1)
{
    asm("mma.sync.aligned.m16n8k16.row.col.f32.f16.f16.f32 "
        "{%0,%1,%2,%3}, {%4,%5,%6,%7}, {%8,%9}, {%0,%1,%2,%3};"
        : "+f"(c0), "+f"(c1), "+f"(c2), "+f"(c3)
        : "r"(a0), "r"(a1), "r"(a2), "r"(a3), "r"(b0), "r"(b1));
}
#define LDSM_X4(r0, r1, r2, r3, addr) \
    asm volatile("ldmatrix.sync.aligned.m8n8.x4.shared.b16 {%0,%1,%2,%3}, [%4];" \
        : "=r"(r0), "=r"(r1), "=r"(r2), "=r"(r3) : "r"(addr))
#define LDSM_X4T(r0, r1, r2, r3, addr) \
    asm volatile("ldmatrix.sync.aligned.m8n8.x4.trans.shared.b16 {%0,%1,%2,%3}, [%4];" \
        : "=r"(r0), "=r"(r1), "=r"(r2), "=r"(r3) : "r"(addr))
#define LDSM_X2(r0, r1, addr) \
    asm volatile("ldmatrix.sync.aligned.m8n8.x2.shared.b16 {%0,%1}, [%2];" \
        : "=r"(r0), "=r"(r1) : "r"(addr))
#define LDSM_X2T(r0, r1, addr) \
    asm volatile("ldmatrix.sync.aligned.m8n8.x2.trans.shared.b16 {%0,%1}, [%2];" \
        : "=r"(r0), "=r"(r1) : "r"(addr))
__device__ __forceinline__ uint32_t smem_to_u32(const void* p) {
    uint32_t a;
    asm("{ .reg .u64 t; cvta.to.shared.u64 t, %1; cvt.u32.u64 %0, t; }" : "=r"(a) : "l"(p));
    return a;
}
__device__ __forceinline__ uint32_t hmul2b(uint32_t a, uint32_t b) {
    __half2 r = __hmul2(*(__half2*)&a, *(__half2*)&b);
    return *(uint32_t*)&r;
}
__device__ __forceinline__ uint32_t pack_h2(float a, float b) {
    __half2 h = __floats2half2_rn(a, b);
    return *(uint32_t*)&h;
}
#define CP_ASYNC16(dst, src) \
    asm volatile("cp.async.cg.shared.global [%0], [%1], 16;" :: "r"(dst), "l"(src))
#define CP_COMMIT() asm volatile("cp.async.commit_group;" ::: "memory")
#define CP_WAIT1()  asm volatile("cp.async.wait_group 1;" ::: "memory")
#define CP_WAIT0()  asm volatile("cp.async.wait_group 0;" ::: "memory")

// ---------------- fused prep: all fp16 conversions + zw1 ----------------
#define PREP_CVT_BLOCKS 7680
#define PREP_BLOCKS (PREP_CVT_BLOCKS + 16)
__global__ void __launch_bounds__(256) prep_kernel(
    const float* __restrict__ x,  const float* __restrict__ WQ,
    const float* __restrict__ WK, const float* __restrict__ WV,
    const float* __restrict__ W1, const float* __restrict__ W2,
    const float* __restrict__ z,
    __half* __restrict__ xh,  __half* __restrict__ WQh,
    __half* __restrict__ WKh, __half* __restrict__ WVh,
    __half* __restrict__ W1h, __half* __restrict__ W2h,
    float* __restrict__ zw1)
{
    const int bid = blockIdx.x;
    if (bid < PREP_CVT_BLOCKS) {
        int g = bid * 256 + threadIdx.x;         // 8-elem group index
        const float* s; __half* d;
        if      (g < 524288)  { s = x;  d = xh;  }
        else if (g < 655360)  { s = WQ; d = WQh; g -= 524288; }
        else if (g < 786432)  { s = WK; d = WKh; g -= 655360; }
        else if (g < 917504)  { s = WV; d = WVh; g -= 786432; }
        else if (g < 1441792) { s = W1; d = W1h; g -= 917504; }
        else                  { s = W2; d = W2h; g -= 1441792; }
        const int i = g * 8;
        float4 v0 = *(const float4*)(s + i);
        float4 v1 = *(const float4*)(s + i + 4);
        __half2 h0 = __floats2half2_rn(v0.x, v0.y);
        __half2 h1 = __floats2half2_rn(v0.z, v0.w);
        __half2 h2 = __floats2half2_rn(v1.x, v1.y);
        __half2 h3 = __floats2half2_rn(v1.z, v1.w);
        *(uint4*)(d + i) = make_uint4(*(uint32_t*)&h0, *(uint32_t*)&h1,
                                      *(uint32_t*)&h2, *(uint32_t*)&h3);
    } else {
        const int n = (bid - PREP_CVT_BLOCKS) * 256 + threadIdx.x;  // 0..4095
        float a0 = 0.f, a1 = 0.f, a2 = 0.f, a3 = 0.f;
#pragma unroll 8
        for (int k = 0; k < DLATc; k++) {
            const float w = W1[(size_t)(Dc + k) * DFFc + n];
            a0 += z[k] * w;
            a1 += z[DLATc + k] * w;
            a2 += z[2 * DLATc + k] * w;
            a3 += z[3 * DLATc + k] * w;
        }
        zw1[n] = a0;
        zw1[DFFc + n] = a1;
        zw1[2 * DFFc + n] = a2;
        zw1[3 * DFFc + n] = a3;
    }
}

// ---------------- fp16 mma.sync GEMM ----------------
#define AROW_B 144
#define BROW_B 272
#define A_BYTES (128 * AROW_B)
#define B_BYTES (64 * BROW_B)
#define BUF_BYTES (A_BYTES + B_BYTES)
#define GEMM_SMEM_BYTES (2 * BUF_BYTES)   // 71680

template<int OUTHALF>
__device__ __forceinline__ void gemm_body(
    char* smem, const __half* __restrict__ A,
    const __half* __restrict__ W, const float* __restrict__ bias,
    const float* __restrict__ zbias,
    void* __restrict__ Cv, int N, int K, int relu, int row0, int col0)
{
    const uint32_t sb = smem_to_u32(smem);
    const int tid  = threadIdx.x;
    const int wid  = tid >> 5, lane = tid & 31;
    const int wm   = wid >> 2, wn = wid & 3;
    const int qrow = lane >> 2, qcol = lane & 3;
    const int l16  = lane & 15, lhi = lane >> 4;
    const int mgrp = lane >> 3;

    float acc[4][4][4];
#pragma unroll
    for (int i = 0; i < 4; i++)
#pragma unroll
        for (int j = 0; j < 4; j++)
#pragma unroll
            for (int r = 0; r < 4; r++) acc[i][j][r] = 0.f;

    const int NC = K / 64;

#define LOAD_CHUNK(c, s) do {                                                        \
    const int _k0 = (c) * 64;                                                        \
    const uint32_t _ab = sb + (uint32_t)((s) * BUF_BYTES);                           \
    const uint32_t _bb = _ab + A_BYTES;                                              \
    _Pragma("unroll")                                                                \
    for (int _u = tid; _u < 1024; _u += 256) {                                       \
        {                                                                            \
            const int _r = _u >> 3, _sg = _u & 7;                                    \
            const __half* _as = A + (size_t)(row0 + _r) * K + _k0 + _sg * 8;         \
            CP_ASYNC16(_ab + (uint32_t)(_r * AROW_B + _sg * 16), _as);               \
        }                                                                            \
        {                                                                            \
            const int _r = _u >> 4, _sg = _u & 15;                                   \
            const __half* _bs = W + (size_t)(_k0 + _r) * N + col0 + _sg * 8;         \
            CP_ASYNC16(_bb + (uint32_t)(_r * BROW_B + _sg * 16), _bs);               \
        }                                                                            \
    }                                                                                \
    CP_COMMIT();                                                                     \
} while (0)

    LOAD_CHUNK(0, 0);
    for (int c = 0; c < NC; c++) {
        const int s = c & 1;
        if (c + 1 < NC) { LOAD_CHUNK(c + 1, s ^ 1); CP_WAIT1(); }
        else            { CP_WAIT0(); }
        __syncthreads();

        const uint32_t ab = sb + (uint32_t)(s * BUF_BYTES);
        const uint32_t bb = ab + A_BYTES;
#pragma unroll
        for (int ks = 0; ks < 4; ks++) {
            const int k = ks * 16;
            uint32_t af[4][4];
#pragma unroll
            for (int mt = 0; mt < 4; mt++) {
                const uint32_t addr = ab
                    + (uint32_t)((wm * 64 + mt * 16 + l16) * AROW_B)
                    + (uint32_t)((k + lhi * 8) * 2);
                LDSM_X4(af[mt][0], af[mt][1], af[mt][2], af[mt][3], addr);
            }
            uint32_t bf[4][2];
#pragma unroll
            for (int ntp = 0; ntp < 2; ntp++) {
                const int row = k + (lane & 7) + (mgrp & 1) * 8;
                const int col = wn * 32 + ntp * 16 + (mgrp >> 1) * 8;
                const uint32_t addr = bb + (uint32_t)(row * BROW_B + col * 2);
                LDSM_X4T(bf[2 * ntp][0], bf[2 * ntp][1],
                         bf[2 * ntp + 1][0], bf[2 * ntp + 1][1], addr);
            }
#pragma unroll
            for (int mt = 0; mt < 4; mt++)
#pragma unroll
                for (int nt = 0; nt < 4; nt++)
                    mma_f16_16x8x16(acc[mt][nt][0], acc[mt][nt][1],
                                    acc[mt][nt][2], acc[mt][nt][3],
                                    af[mt][0], af[mt][1], af[mt][2], af[mt][3],
                                    bf[nt][0], bf[nt][1]);
        }
        __syncthreads();
    }

    const float* zb = zbias ? (zbias + (size_t)(row0 >> 10) * N) : nullptr;
#pragma unroll
    for (int mt = 0; mt < 4; mt++) {
        const int r = row0 + wm * 64 + mt * 16 + qrow;
#pragma unroll
        for (int nt = 0; nt < 4; nt++) {
            const int cc = col0 + wn * 32 + nt * 8 + 2 * qcol;
            float2 v0, v1;
            v0.x = acc[mt][nt][0]; v0.y = acc[mt][nt][1];
            v1.x = acc[mt][nt][2]; v1.y = acc[mt][nt][3];
            if (bias) {
                float bx = bias[cc], by = bias[cc + 1];
                if (zb) { bx += zb[cc]; by += zb[cc + 1]; }
                v0.x += bx; v0.y += by; v1.x += bx; v1.y += by;
            }
            if (relu) {
                v0.x = fmaxf(v0.x, 0.f); v0.y = fmaxf(v0.y, 0.f);
                v1.x = fmaxf(v1.x, 0.f); v1.y = fmaxf(v1.y, 0.f);
            }
            if (OUTHALF) {
                __half* Ch = (__half*)Cv;
                __half2 h0 = __floats2half2_rn(v0.x, v0.y);
                __half2 h1 = __floats2half2_rn(v1.x, v1.y);
                *(__half2*)(Ch + (size_t)r * N + cc)       = h0;
                *(__half2*)(Ch + (size_t)(r + 8) * N + cc) = h1;
            } else {
                float* C = (float*)Cv;
                *(float2*)(C + (size_t)r * N + cc)       = v0;
                *(float2*)(C + (size_t)(r + 8) * N + cc) = v1;
            }
        }
    }
#undef LOAD_CHUNK
}

template<int OUTHALF>
__global__ void __launch_bounds__(256, 2) mma_gemm(
    const __half* __restrict__ A, const __half* __restrict__ W,
    const float* __restrict__ bias, const float* __restrict__ zbias,
    void* __restrict__ C, int N, int K, int relu)
{
    extern __shared__ char smem[];
    gemm_body<OUTHALF>(smem, A, W, bias, zbias, C, N, K, relu,
                       blockIdx.y * 128, blockIdx.x * 128);
}

__global__ void __launch_bounds__(256, 2) qkv_gemm(
    const __half* __restrict__ xh,
    const __half* __restrict__ WQ, const __half* __restrict__ WK,
    const __half* __restrict__ WV,
    __half* __restrict__ Q, __half* __restrict__ K, __half* __restrict__ V)
{
    extern __shared__ char smem[];
    const int sel  = blockIdx.x >> 3;
    const int col0 = (blockIdx.x & 7) << 7;
    const __half* W = (sel == 0) ? WQ : (sel == 1) ? WK : WV;
    __half*       C = (sel == 0) ? Q  : (sel == 1) ? K  : V;
    gemm_body<1>(smem, xh, W, nullptr, nullptr, C, Dc, Dc, 0,
                 blockIdx.y * 128, col0);
}

// ---------------- fp16 flash attention (R13 static-loop schedule) ----------
#define KROW 72
__global__ void __launch_bounds__(128, 4) attn_kernel(
    const __half* __restrict__ Q, const __half* __restrict__ K,
    const __half* __restrict__ V, const int* __restrict__ mask,
    __half* __restrict__ O)
{
    __shared__ __half Ks[64 * KROW];
    __shared__ __half Vs[64 * KROW];
    __shared__ int    km[64];
    const int qt = gridDim.x - 1 - blockIdx.x;   // LPT: longest first
    const int h = blockIdx.y, b = blockIdx.z;
    const int q0 = qt * 64;
    const int tid = threadIdx.x;
    const int w = tid >> 5, lane = tid & 31;
    const int qrow = lane >> 2, qcol = lane & 3;
    const int l16 = lane & 15, lhi = lane >> 4;
    const size_t base = ((size_t)b * Sc) * Dc + (size_t)h * DHc;
    const uint32_t ksb = smem_to_u32(Ks);
    const uint32_t vsb = smem_to_u32(Vs);

    for (int i = tid; i < 64 * 8; i += 128) {
        const int r = i >> 3, c = (i & 7) * 8;
        *(uint4*)(Ks + r * KROW + c) =
            *(const uint4*)(Q + base + (size_t)(q0 + r) * Dc + c);
    }
    __syncthreads();
    uint32_t qf[4][4];
    {
        const uint32_t s2 = 0x30003000u;   // half2(0.125, 0.125)
#pragma unroll
        for (int ks = 0; ks < 4; ks++) {
            const uint32_t addr = ksb
                + (uint32_t)(((w * 16 + l16) * KROW + ks * 16 + lhi * 8) * 2);
            LDSM_X4(qf[ks][0], qf[ks][1], qf[ks][2], qf[ks][3], addr);
            qf[ks][0] = hmul2b(qf[ks][0], s2);
            qf[ks][1] = hmul2b(qf[ks][1], s2);
            qf[ks][2] = hmul2b(qf[ks][2], s2);
            qf[ks][3] = hmul2b(qf[ks][3], s2);
        }
    }
    const int qg0 = q0 + w * 16 + qrow, qg1 = qg0 + 8;
    const int mq0 = mask[b * Sc + qg0], mq1 = mask[b * Sc + qg1];

    float m0 = -1e30f, m1 = -1e30f, l0 = 0.f, l1 = 0.f;
    float oacc[8][4];
#pragma unroll
    for (int nt = 0; nt < 8; nt++)
#pragma unroll
        for (int e = 0; e < 4; e++) oacc[nt][e] = 0.f;

    for (int kt = 0; kt <= qt; kt++) {
        const int k0 = kt * 64;
        __syncthreads();
        for (int i = tid; i < 64 * 8; i += 128) {
            const int r = i >> 3, c = (i & 7) * 8;
            *(uint4*)(Ks + r * KROW + c) =
                *(const uint4*)(K + base + (size_t)(k0 + r) * Dc + c);
            *(uint4*)(Vs + r * KROW + c) =
                *(const uint4*)(V + base + (size_t)(k0 + r) * Dc + c);
        }
        if (tid < 64) km[tid] = mask[b * Sc + k0 + tid];
        __syncthreads();

        float sc[8][4];
#pragma unroll
        for (int nt = 0; nt < 8; nt++) {
            sc[nt][0] = sc[nt][1] = sc[nt][2] = sc[nt][3] = 0.f;
#pragma unroll
            for (int ks = 0; ks < 4; ks++) {
                uint32_t b0, b1;
                const uint32_t addr = ksb
                    + (uint32_t)(((nt * 8 + (l16 & 7)) * KROW
                                  + ks * 16 + (l16 >> 3) * 8) * 2);
                LDSM_X2(b0, b1, addr);
                mma_f16_16x8x16(sc[nt][0], sc[nt][1], sc[nt][2], sc[nt][3],
                                qf[ks][0], qf[ks][1], qf[ks][2], qf[ks][3], b0, b1);
            }
        }
        float mt0 = -1e30f, mt1 = -1e30f;
#pragma unroll
        for (int nt = 0; nt < 8; nt++) {
            const int kk0 = nt * 8 + 2 * qcol, kk1 = kk0 + 1;
            const int msk0 = km[kk0], msk1 = km[kk1];
            if ((k0 + kk0) > qg0 || msk0 == 0) sc[nt][0] = -1e30f;
            if ((k0 + kk1) > qg0 || msk1 == 0) sc[nt][1] = -1e30f;
            if ((k0 + kk0) > qg1 || msk0 == 0) sc[nt][2] = -1e30f;
            if ((k0 + kk1) > qg1 || msk1 == 0) sc[nt][3] = -1e30f;
            mt0 = fmaxf(mt0, fmaxf(sc[nt][0], sc[nt][1]));
            mt1 = fmaxf(mt1, fmaxf(sc[nt][2], sc[nt][3]));
        }
        mt0 = fmaxf(mt0, __shfl_xor_sync(0xffffffffu, mt0, 1));
        mt0 = fmaxf(mt0, __shfl_xor_sync(0xffffffffu, mt0, 2));
        mt1 = fmaxf(mt1, __shfl_xor_sync(0xffffffffu, mt1, 1));
        mt1 = fmaxf(mt1, __shfl_xor_sync(0xffffffffu, mt1, 2));
        const float mn0 = fmaxf(m0, mt0), mn1 = fmaxf(m1, mt1);
        const float sc0 = __expf(m0 - mn0), sc1 = __expf(m1 - mn1);
        float lt0 = 0.f, lt1 = 0.f;
#pragma unroll
        for (int nt = 0; nt < 8; nt++) {
            sc[nt][0] = __expf(sc[nt][0] - mn0);
            sc[nt][1] = __expf(sc[nt][1] - mn0);
            sc[nt][2] = __expf(sc[nt][2] - mn1);
            sc[nt][3] = __expf(sc[nt][3] - mn1);
            lt0 += sc[nt][0] + sc[nt][1];
            lt1 += sc[nt][2] + sc[nt][3];
        }
        lt0 += __shfl_xor_sync(0xffffffffu, lt0, 1);
        lt0 += __shfl_xor_sync(0xffffffffu, lt0, 2);
        lt1 += __shfl_xor_sync(0xffffffffu, lt1, 1);
        lt1 += __shfl_xor_sync(0xffffffffu, lt1, 2);
        l0 = l0 * sc0 + lt0; m0 = mn0;
        l1 = l1 * sc1 + lt1; m1 = mn1;
#pragma unroll
        for (int nt = 0; nt < 8; nt++) {
            oacc[nt][0] *= sc0; oacc[nt][1] *= sc0;
            oacc[nt][2] *= sc1; oacc[nt][3] *= sc1;
        }

        uint32_t pf[4][4];
#pragma unroll
        for (int ks = 0; ks < 4; ks++) {
            pf[ks][0] = pack_h2(sc[2 * ks][0],     sc[2 * ks][1]);
            pf[ks][1] = pack_h2(sc[2 * ks][2],     sc[2 * ks][3]);
            pf[ks][2] = pack_h2(sc[2 * ks + 1][0], sc[2 * ks + 1][1]);
            pf[ks][3] = pack_h2(sc[2 * ks + 1][2], sc[2 * ks + 1][3]);
        }
#pragma unroll
        for (int nt = 0; nt < 8; nt++) {
#pragma unroll
            for (int ks = 0; ks < 4; ks++) {
                uint32_t b0, b1;
                const uint32_t addr = vsb
                    + (uint32_t)(((ks * 16 + l16) * KROW + nt * 8) * 2);
                LDSM_X2T(b0, b1, addr);
                mma_f16_16x8x16(oacc[nt][0], oacc[nt][1], oacc[nt][2], oacc[nt][3],
                                pf[ks][0], pf[ks][1], pf[ks][2], pf[ks][3], b0, b1);
            }
        }
    }

    const float inv0 = (mq0 != 0) ? (1.0f / l0) : 0.f;
    const float inv1 = (mq1 != 0) ? (1.0f / l1) : 0.f;
    __half* o0 = O + base + (size_t)qg0 * Dc;
    __half* o1 = O + base + (size_t)qg1 * Dc;
#pragma unroll
    for (int nt = 0; nt < 8; nt++) {
        const int cc = nt * 8 + 2 * qcol;
        __half2 h0 = __floats2half2_rn(oacc[nt][0] * inv0, oacc[nt][1] * inv0);
        __half2 h1 = __floats2half2_rn(oacc[nt][2] * inv1, oacc[nt][3] * inv1);
        *(__half2*)(o0 + cc) = h0;
        *(__half2*)(o1 + cc) = h1;
    }
}

// ---------------- layernorm (vectorized, R14 versions) ----------
__device__ __forceinline__ float block_sum(float v, float* red) {
#pragma unroll
    for (int o = 16; o > 0; o >>= 1) v += __shfl_xor_sync(0xffffffffu, v, o);
    const int lane = threadIdx.x & 31, w = threadIdx.x >> 5;
    __syncthreads();
    if (lane == 0) red[w] = v;
    __syncthreads();
    float s = 0.f;
#pragma unroll
    for (int i = 0; i < 8; i++) s += red[i];
    return s;
}

__global__ void __launch_bounds__(256) ln12_kernel(
    const float* __restrict__ x, const __half* __restrict__ o,
    const float* __restrict__ cond,
    const float* __restrict__ g1, const float* __restrict__ b1,
    const float* __restrict__ g2, const float* __restrict__ b2,
    __half* __restrict__ out2h)
{
    __shared__ float red[8];
    const int row = blockIdx.x;
    const int bb  = row >> 10;
    const int d0  = threadIdx.x * 4;
    float t[4];
    {
        float4 xv = *(const float4*)(x + (size_t)row * Dc + d0);
        uint2  ov = *(const uint2*)(o + (size_t)row * Dc + d0);
        float2 o0 = __half22float2(*(__half2*)&ov.x);
        float2 o1 = __half22float2(*(__half2*)&ov.y);
        t[0] = xv.x + o0.x; t[1] = xv.y + o0.y;
        t[2] = xv.z + o1.x; t[3] = xv.w + o1.y;
    }
    float s = t[0] + t[1] + t[2] + t[3];
    float mu = block_sum(s, red) * (1.f / 1024.f);
    float vs = 0.f;
#pragma unroll
    for (int k = 0; k < 4; k++) { float dv = t[k] - mu; vs += dv * dv; }
    float var = block_sum(vs, red) * (1.f / 1024.f);
    float inv = rsqrtf(var + 1e-3f);
    {
        float4 gv = *(const float4*)(g1 + d0);
        float4 bv = *(const float4*)(b1 + d0);
        float4 cv = *(const float4*)(cond + (size_t)bb * Dc + d0);
        t[0] = (t[0] - mu) * inv * gv.x + bv.x + cv.x;
        t[1] = (t[1] - mu) * inv * gv.y + bv.y + cv.y;
        t[2] = (t[2] - mu) * inv * gv.z + bv.z + cv.z;
        t[3] = (t[3] - mu) * inv * gv.w + bv.w + cv.w;
    }
    s = t[0] + t[1] + t[2] + t[3];
    mu = block_sum(s, red) * (1.f / 1024.f);
    vs = 0.f;
#pragma unroll
    for (int k = 0; k < 4; k++) { float dv = t[k] - mu; vs += dv * dv; }
    var = block_sum(vs, red) * (1.f / 1024.f);
    inv = rsqrtf(var + 1e-3f);
    {
        float4 gv = *(const float4*)(g2 + d0);
        float4 bv = *(const float4*)(b2 + d0);
        float y0 = (t[0] - mu) * inv * gv.x + bv.x;
        float y1 = (t[1] - mu) * inv * gv.y + bv.y;
        float y2 = (t[2] - mu) * inv * gv.z + bv.z;
        float y3 = (t[3] - mu) * inv * gv.w + bv.w;
        __half2 h0 = __floats2half2_rn(y0, y1);
        __half2 h1 = __floats2half2_rn(y2, y3);
        *(uint2*)(out2h + (size_t)row * Dc + d0) =
            make_uint2(*(uint32_t*)&h0, *(uint32_t*)&h1);
    }
}

__global__ void __launch_bounds__(256) ln3_kernel(
    const __half* __restrict__ a, const float* __restrict__ f,
    const float* __restrict__ g3, const float* __restrict__ b3,
    float* __restrict__ out)
{
    __shared__ float red[8];
    const int row = blockIdx.x;
    const int d0  = threadIdx.x * 4;
    float t[4];
    {
        uint2  av = *(const uint2*)(a + (size_t)row * Dc + d0);
        float4 fv = *(const float4*)(f + (size_t)row * Dc + d0);
        float2 a0 = __half22float2(*(__half2*)&av.x);
        float2 a1 = __half22float2(*(__half2*)&av.y);
        t[0] = a0.x + fv.x; t[1] = a0.y + fv.y;
        t[2] = a1.x + fv.z; t[3] = a1.y + fv.w;
    }
    float s = t[0] + t[1] + t[2] + t[3];
    float mu = block_sum(s, red) * (1.f / 1024.f);
    float vs = 0.f;
#pragma unroll
    for (int k = 0; k < 4; k++) { float dv = t[k] - mu; vs += dv * dv; }
    float var = block_sum(vs, red) * (1.f / 1024.f);
    float inv = rsqrtf(var + 1e-3f);
    {
        float4 gv = *(const float4*)(g3 + d0);
        float4 bv = *(const float4*)(b3 + d0);
        float4 ov;
        ov.x = (t[0] - mu) * inv * gv.x + bv.x;
        ov.y = (t[1] - mu) * inv * gv.y + bv.y;
        ov.z = (t[2] - mu) * inv * gv.z + bv.z;
        ov.w = (t[3] - mu) * inv * gv.w + bv.w;
        *(float4*)(out + (size_t)row * Dc + d0) = ov;
    }
}

// ---------------- launch ----------------
extern "C" void kernel_launch(void* const* d_in, const int* in_sizes, int n_in,
                              void* d_out, int out_size) {
    const float* x    = (const float*)d_in[0];
    const float* z    = (const float*)d_in[1];
    const float* cond = (const float*)d_in[2];
    const int*   xm   = (const int*)  d_in[3];
    const float* WQ   = (const float*)d_in[4];
    const float* WK   = (const float*)d_in[5];
    const float* WV   = (const float*)d_in[6];
    const float* W1   = (const float*)d_in[7];
    const float* b1   = (const float*)d_in[8];
    const float* W2   = (const float*)d_in[9];
    const float* b2   = (const float*)d_in[10];
    const float* g1   = (const float*)d_in[11];
    const float* be1  = (const float*)d_in[12];
    const float* g2   = (const float*)d_in[13];
    const float* be2  = (const float*)d_in[14];
    const float* g3   = (const float*)d_in[15];
    const float* be3  = (const float*)d_in[16];
    float* out = (float*)d_out;

    float *pF, *pZW1;
    __half *pOh, *pQh, *pKh, *pVh, *pxh, *pO2h, *pHh, *pWQh, *pWKh, *pWVh, *pW1h, *pW2h;
    cudaGetSymbolAddress((void**)&pF,   g_F);
    cudaGetSymbolAddress((void**)&pZW1, g_ZW1);
    cudaGetSymbolAddress((void**)&pOh,  g_Oh);
    cudaGetSymbolAddress((void**)&pQh,  g_Qh);
    cudaGetSymbolAddress((void**)&pKh,  g_Kh);
    cudaGetSymbolAddress((void**)&pVh,  g_Vh);
    cudaGetSymbolAddress((void**)&pxh,  g_xh);
    cudaGetSymbolAddress((void**)&pO2h, g_O2h);
    cudaGetSymbolAddress((void**)&pHh,  g_Hh);
    cudaGetSymbolAddress((void**)&pWQh, g_WQh);
    cudaGetSymbolAddress((void**)&pWKh, g_WKh);
    cudaGetSymbolAddress((void**)&pWVh, g_WVh);
    cudaGetSymbolAddress((void**)&pW1h, g_W1h);
    cudaGetSymbolAddress((void**)&pW2h, g_W2h);

    cudaFuncSetAttribute(mma_gemm<0>, cudaFuncAttributeMaxDynamicSharedMemorySize,
                         GEMM_SMEM_BYTES);
    cudaFuncSetAttribute(mma_gemm<1>, cudaFuncAttributeMaxDynamicSharedMemorySize,
                         GEMM_SMEM_BYTES);
    cudaFuncSetAttribute(qkv_gemm, cudaFuncAttributeMaxDynamicSharedMemorySize,
                         GEMM_SMEM_BYTES);

    prep_kernel<<<PREP_BLOCKS, 256>>>(x, WQ, WK, WV, W1, W2, z,
                                      pxh, pWQh, pWKh, pWVh, pW1h, pW2h, pZW1);

    qkv_gemm<<<dim3(24, Mrows / 128), 256, GEMM_SMEM_BYTES>>>(
        pxh, pWQh, pWKh, pWVh, pQh, pKh, pVh);

    attn_kernel<<<dim3(Sc / 64, Hc, Bc), 128>>>(pQh, pKh, pVh, xm, pOh);

    ln12_kernel<<<Mrows, 256>>>(x, pOh, cond, g1, be1, g2, be2, pO2h);

    mma_gemm<1><<<dim3(DFFc / 128, Mrows / 128), 256, GEMM_SMEM_BYTES>>>(
        pO2h, pW1h, b1, pZW1, pHh, DFFc, Dc, 1);
    mma_gemm<0><<<dim3(Dc / 128, Mrows / 128), 256, GEMM_SMEM_BYTES>>>(
        pHh, pW2h, b2, nullptr, pF, Dc, DFFc, 0);

    ln3_kernel<<<Mrows, 256>>>(pO2h, pF, g3, be3, out);
}

// round 16
// speedup vs baseline: 1.1793x; 1.1222x over previous
#include <cuda_runtime.h>
#include <cuda_fp16.h>
#include <cstdint>

#define Bc   4
#define Sc   1024
#define Dc   1024
#define Hc   16
#define DHc  64
#define DFFc 4096
#define DLATc 256
#define Mrows (Bc * Sc)   // 4096

// ---------------- scratch (no cudaMalloc allowed) ----------------
__device__ float  g_ZW1[Bc * DFFc];
__device__ __half g_Fh [Mrows * Dc];
__device__ __half g_Oh [Mrows * Dc];
__device__ __half g_Qh [Mrows * Dc];
__device__ __half g_Kh [Mrows * Dc];
__device__ __half g_Vh [Mrows * Dc];
__device__ __half g_xh [Mrows * Dc];
__device__ __half g_O2h[Mrows * Dc];
__device__ __half g_Hh [Mrows * DFFc];
__device__ __half g_WQh[Dc * Dc];
__device__ __half g_WKh[Dc * Dc];
__device__ __half g_WVh[Dc * Dc];
__device__ __half g_W1h[Dc * DFFc];     // first 1024 rows of W1 only
__device__ __half g_W2h[DFFc * Dc];

// ---------------- PTX helpers (base ISA only) ----------------
__device__ __forceinline__ void mma_f16_16x8x16(
    float& c0, float& c1, float& c2, float& c3,
    uint32_t a0, uint32_t a1, uint32_t a2, uint32_t a3,
    uint32_t b0, uint32_t b1)
{
    asm("mma.sync.aligned.m16n8k16.row.col.f32.f16.f16.f32 "
        "{%0,%1,%2,%3}, {%4,%5,%6,%7}, {%8,%9}, {%0,%1,%2,%3};"
        : "+f"(c0), "+f"(c1), "+f"(c2), "+f"(c3)
        : "r"(a0), "r"(a1), "r"(a2), "r"(a3), "r"(b0), "r"(b1));
}
#define LDSM_X4(r0, r1, r2, r3, addr) \
    asm volatile("ldmatrix.sync.aligned.m8n8.x4.shared.b16 {%0,%1,%2,%3}, [%4];" \
        : "=r"(r0), "=r"(r1), "=r"(r2), "=r"(r3) : "r"(addr))
#define LDSM_X4T(r0, r1, r2, r3, addr) \
    asm volatile("ldmatrix.sync.aligned.m8n8.x4.trans.shared.b16 {%0,%1,%2,%3}, [%4];" \
        : "=r"(r0), "=r"(r1), "=r"(r2), "=r"(r3) : "r"(addr))
#define LDSM_X2(r0, r1, addr) \
    asm volatile("ldmatrix.sync.aligned.m8n8.x2.shared.b16 {%0,%1}, [%2];" \
        : "=r"(r0), "=r"(r1) : "r"(addr))
#define LDSM_X2T(r0, r1, addr) \
    asm volatile("ldmatrix.sync.aligned.m8n8.x2.trans.shared.b16 {%0,%1}, [%2];" \
        : "=r"(r0), "=r"(r1) : "r"(addr))
__device__ __forceinline__ uint32_t smem_to_u32(const void* p) {
    uint32_t a;
    asm("{ .reg .u64 t; cvta.to.shared.u64 t, %1; cvt.u32.u64 %0, t; }" : "=r"(a) : "l"(p));
    return a;
}
__device__ __forceinline__ uint32_t hmul2b(uint32_t a, uint32_t b) {
    __half2 r = __hmul2(*(__half2*)&a, *(__half2*)&b);
    return *(uint32_t*)&r;
}
__device__ __forceinline__ uint32_t pack_h2(float a, float b) {
    __half2 h = __floats2half2_rn(a, b);
    return *(uint32_t*)&h;
}
#define CP_ASYNC16(dst, src) \
    asm volatile("cp.async.cg.shared.global [%0], [%1], 16;" :: "r"(dst), "l"(src))
#define CP_COMMIT() asm volatile("cp.async.commit_group;" ::: "memory")
#define CP_WAIT1()  asm volatile("cp.async.wait_group 1;" ::: "memory")
#define CP_WAIT0()  asm volatile("cp.async.wait_group 0;" ::: "memory")

// ---------------- prep A (critical path): x, WQ, WK, WV -> fp16 -------------
// groups: x 524288 | WQ 131072 | WK 131072 | WV 131072 = 917504 -> 3584 blocks
#define PREPA_BLOCKS 3584
__global__ void __launch_bounds__(256) prep_a_kernel(
    const float* __restrict__ x,  const float* __restrict__ WQ,
    const float* __restrict__ WK, const float* __restrict__ WV,
    __half* __restrict__ xh,  __half* __restrict__ WQh,
    __half* __restrict__ WKh, __half* __restrict__ WVh)
{
    int g = blockIdx.x * 256 + threadIdx.x;
    const float* s; __half* d;
    if      (g < 524288) { s = x;  d = xh;  }
    else if (g < 655360) { s = WQ; d = WQh; g -= 524288; }
    else if (g < 786432) { s = WK; d = WKh; g -= 655360; }
    else                 { s = WV; d = WVh; g -= 786432; }
    const int i = g * 8;
    float4 v0 = *(const float4*)(s + i);
    float4 v1 = *(const float4*)(s + i + 4);
    __half2 h0 = __floats2half2_rn(v0.x, v0.y);
    __half2 h1 = __floats2half2_rn(v0.z, v0.w);
    __half2 h2 = __floats2half2_rn(v1.x, v1.y);
    __half2 h3 = __floats2half2_rn(v1.z, v1.w);
    *(uint4*)(d + i) = make_uint4(*(uint32_t*)&h0, *(uint32_t*)&h1,
                                  *(uint32_t*)&h2, *(uint32_t*)&h3);
}

// ---------------- prep B (side stream): W1, W2 -> fp16 + zw1 ----------------
// groups: W1p 524288 | W2 524288 = 1048576 -> 4096 blocks; +16 zw1 blocks
#define PREPB_CVT_BLOCKS 4096
#define PREPB_BLOCKS (PREPB_CVT_BLOCKS + 16)
__global__ void __launch_bounds__(256) prep_b_kernel(
    const float* __restrict__ W1, const float* __restrict__ W2,
    const float* __restrict__ z,
    __half* __restrict__ W1h, __half* __restrict__ W2h,
    float* __restrict__ zw1)
{
    const int bid = blockIdx.x;
    if (bid < PREPB_CVT_BLOCKS) {
        int g = bid * 256 + threadIdx.x;
        const float* s; __half* d;
        if (g < 524288) { s = W1; d = W1h; }
        else            { s = W2; d = W2h; g -= 524288; }
        const int i = g * 8;
        float4 v0 = *(const float4*)(s + i);
        float4 v1 = *(const float4*)(s + i + 4);
        __half2 h0 = __floats2half2_rn(v0.x, v0.y);
        __half2 h1 = __floats2half2_rn(v0.z, v0.w);
        __half2 h2 = __floats2half2_rn(v1.x, v1.y);
        __half2 h3 = __floats2half2_rn(v1.z, v1.w);
        *(uint4*)(d + i) = make_uint4(*(uint32_t*)&h0, *(uint32_t*)&h1,
                                      *(uint32_t*)&h2, *(uint32_t*)&h3);
    } else {
        const int n = (bid - PREPB_CVT_BLOCKS) * 256 + threadIdx.x;  // 0..4095
        float a0 = 0.f, a1 = 0.f, a2 = 0.f, a3 = 0.f;
#pragma unroll 8
        for (int k = 0; k < DLATc; k++) {
            const float w = W1[(size_t)(Dc + k) * DFFc + n];
            a0 += z[k] * w;
            a1 += z[DLATc + k] * w;
            a2 += z[2 * DLATc + k] * w;
            a3 += z[3 * DLATc + k] * w;
        }
        zw1[n] = a0;
        zw1[DFFc + n] = a1;
        zw1[2 * DFFc + n] = a2;
        zw1[3 * DFFc + n] = a3;
    }
}

// ---------------- fp16 mma.sync GEMM ----------------
#define AROW_B 144
#define BROW_B 272
#define A_BYTES (128 * AROW_B)
#define B_BYTES (64 * BROW_B)
#define BUF_BYTES (A_BYTES + B_BYTES)
#define GEMM_SMEM_BYTES (2 * BUF_BYTES)   // 71680

template<int OUTHALF>
__device__ __forceinline__ void gemm_body(
    char* smem, const __half* __restrict__ A,
    const __half* __restrict__ W, const float* __restrict__ bias,
    const float* __restrict__ zbias,
    void* __restrict__ Cv, int N, int K, int relu, int row0, int col0)
{
    const uint32_t sb = smem_to_u32(smem);
    const int tid  = threadIdx.x;
    const int wid  = tid >> 5, lane = tid & 31;
    const int wm   = wid >> 2, wn = wid & 3;
    const int qrow = lane >> 2, qcol = lane & 3;
    const int l16  = lane & 15, lhi = lane >> 4;
    const int mgrp = lane >> 3;

    float acc[4][4][4];
#pragma unroll
    for (int i = 0; i < 4; i++)
#pragma unroll
        for (int j = 0; j < 4; j++)
#pragma unroll
            for (int r = 0; r < 4; r++) acc[i][j][r] = 0.f;

    const int NC = K / 64;

#define LOAD_CHUNK(c, s) do {                                                        \
    const int _k0 = (c) * 64;                                                        \
    const uint32_t _ab = sb + (uint32_t)((s) * BUF_BYTES);                           \
    const uint32_t _bb = _ab + A_BYTES;                                              \
    _Pragma("unroll")                                                                \
    for (int _u = tid; _u < 1024; _u += 256) {                                       \
        {                                                                            \
            const int _r = _u >> 3, _sg = _u & 7;                                    \
            const __half* _as = A + (size_t)(row0 + _r) * K + _k0 + _sg * 8;         \
            CP_ASYNC16(_ab + (uint32_t)(_r * AROW_B + _sg * 16), _as);               \
        }                                                                            \
        {                                                                            \
            const int _r = _u >> 4, _sg = _u & 15;                                   \
            const __half* _bs = W + (size_t)(_k0 + _r) * N + col0 + _sg * 8;         \
            CP_ASYNC16(_bb + (uint32_t)(_r * BROW_B + _sg * 16), _bs);               \
        }                                                                            \
    }                                                                                \
    CP_COMMIT();                                                                     \
} while (0)

    LOAD_CHUNK(0, 0);
    for (int c = 0; c < NC; c++) {
        const int s = c & 1;
        if (c + 1 < NC) { LOAD_CHUNK(c + 1, s ^ 1); CP_WAIT1(); }
        else            { CP_WAIT0(); }
        __syncthreads();

        const uint32_t ab = sb + (uint32_t)(s * BUF_BYTES);
        const uint32_t bb = ab + A_BYTES;
#pragma unroll
        for (int ks = 0; ks < 4; ks++) {
            const int k = ks * 16;
            uint32_t af[4][4];
#pragma unroll
            for (int mt = 0; mt < 4; mt++) {
                const uint32_t addr = ab
                    + (uint32_t)((wm * 64 + mt * 16 + l16) * AROW_B)
                    + (uint32_t)((k + lhi * 8) * 2);
                LDSM_X4(af[mt][0], af[mt][1], af[mt][2], af[mt][3], addr);
            }
            uint32_t bf[4][2];
#pragma unroll
            for (int ntp = 0; ntp < 2; ntp++) {
                const int row = k + (lane & 7) + (mgrp & 1) * 8;
                const int col = wn * 32 + ntp * 16 + (mgrp >> 1) * 8;
                const uint32_t addr = bb + (uint32_t)(row * BROW_B + col * 2);
                LDSM_X4T(bf[2 * ntp][0], bf[2 * ntp][1],
                         bf[2 * ntp + 1][0], bf[2 * ntp + 1][1], addr);
            }
#pragma unroll
            for (int mt = 0; mt < 4; mt++)
#pragma unroll
                for (int nt = 0; nt < 4; nt++)
                    mma_f16_16x8x16(acc[mt][nt][0], acc[mt][nt][1],
                                    acc[mt][nt][2], acc[mt][nt][3],
                                    af[mt][0], af[mt][1], af[mt][2], af[mt][3],
                                    bf[nt][0], bf[nt][1]);
        }
        __syncthreads();
    }

    const float* zb = zbias ? (zbias + (size_t)(row0 >> 10) * N) : nullptr;
#pragma unroll
    for (int mt = 0; mt < 4; mt++) {
        const int r = row0 + wm * 64 + mt * 16 + qrow;
#pragma unroll
        for (int nt = 0; nt < 4; nt++) {
            const int cc = col0 + wn * 32 + nt * 8 + 2 * qcol;
            float2 v0, v1;
            v0.x = acc[mt][nt][0]; v0.y = acc[mt][nt][1];
            v1.x = acc[mt][nt][2]; v1.y = acc[mt][nt][3];
            if (bias) {
                float bx = bias[cc], by = bias[cc + 1];
                if (zb) { bx += zb[cc]; by += zb[cc + 1]; }
                v0.x += bx; v0.y += by; v1.x += bx; v1.y += by;
            }
            if (relu) {
                v0.x = fmaxf(v0.x, 0.f); v0.y = fmaxf(v0.y, 0.f);
                v1.x = fmaxf(v1.x, 0.f); v1.y = fmaxf(v1.y, 0.f);
            }
            if (OUTHALF) {
                __half* Ch = (__half*)Cv;
                __half2 h0 = __floats2half2_rn(v0.x, v0.y);
                __half2 h1 = __floats2half2_rn(v1.x, v1.y);
                *(__half2*)(Ch + (size_t)r * N + cc)       = h0;
                *(__half2*)(Ch + (size_t)(r + 8) * N + cc) = h1;
            } else {
                float* C = (float*)Cv;
                *(float2*)(C + (size_t)r * N + cc)       = v0;
                *(float2*)(C + (size_t)(r + 8) * N + cc) = v1;
            }
        }
    }
#undef LOAD_CHUNK
}

template<int OUTHALF>
__global__ void __launch_bounds__(256, 2) mma_gemm(
    const __half* __restrict__ A, const __half* __restrict__ W,
    const float* __restrict__ bias, const float* __restrict__ zbias,
    void* __restrict__ C, int N, int K, int relu)
{
    extern __shared__ char smem[];
    gemm_body<OUTHALF>(smem, A, W, bias, zbias, C, N, K, relu,
                       blockIdx.y * 128, blockIdx.x * 128);
}

__global__ void __launch_bounds__(256, 2) qkv_gemm(
    const __half* __restrict__ xh,
    const __half* __restrict__ WQ, const __half* __restrict__ WK,
    const __half* __restrict__ WV,
    __half* __restrict__ Q, __half* __restrict__ K, __half* __restrict__ V)
{
    extern __shared__ char smem[];
    const int sel  = blockIdx.x >> 3;
    const int col0 = (blockIdx.x & 7) << 7;
    const __half* W = (sel == 0) ? WQ : (sel == 1) ? WK : WV;
    __half*       C = (sel == 0) ? Q  : (sel == 1) ? K  : V;
    gemm_body<1>(smem, xh, W, nullptr, nullptr, C, Dc, Dc, 0,
                 blockIdx.y * 128, col0);
}

// ---------------- fp16 flash attention (static-loop schedule) ----------
#define KROW 72
__global__ void __launch_bounds__(128, 4) attn_kernel(
    const __half* __restrict__ Q, const __half* __restrict__ K,
    const __half* __restrict__ V, const int* __restrict__ mask,
    __half* __restrict__ O)
{
    __shared__ __half Ks[64 * KROW];
    __shared__ __half Vs[64 * KROW];
    __shared__ int    km[64];
    const int qt = gridDim.x - 1 - blockIdx.x;   // LPT: longest first
    const int h = blockIdx.y, b = blockIdx.z;
    const int q0 = qt * 64;
    const int tid = threadIdx.x;
    const int w = tid >> 5, lane = tid & 31;
    const int qrow = lane >> 2, qcol = lane & 3;
    const int l16 = lane & 15, lhi = lane >> 4;
    const size_t base = ((size_t)b * Sc) * Dc + (size_t)h * DHc;
    const uint32_t ksb = smem_to_u32(Ks);
    const uint32_t vsb = smem_to_u32(Vs);

    for (int i = tid; i < 64 * 8; i += 128) {
        const int r = i >> 3, c = (i & 7) * 8;
        *(uint4*)(Ks + r * KROW + c) =
            *(const uint4*)(Q + base + (size_t)(q0 + r) * Dc + c);
    }
    __syncthreads();
    uint32_t qf[4][4];
    {
        const uint32_t s2 = 0x30003000u;   // half2(0.125, 0.125)
#pragma unroll
        for (int ks = 0; ks < 4; ks++) {
            const uint32_t addr = ksb
                + (uint32_t)(((w * 16 + l16) * KROW + ks * 16 + lhi * 8) * 2);
            LDSM_X4(qf[ks][0], qf[ks][1], qf[ks][2], qf[ks][3], addr);
            qf[ks][0] = hmul2b(qf[ks][0], s2);
            qf[ks][1] = hmul2b(qf[ks][1], s2);
            qf[ks][2] = hmul2b(qf[ks][2], s2);
            qf[ks][3] = hmul2b(qf[ks][3], s2);
        }
    }
    const int qg0 = q0 + w * 16 + qrow, qg1 = qg0 + 8;
    const int mq0 = mask[b * Sc + qg0], mq1 = mask[b * Sc + qg1];

    float m0 = -1e30f, m1 = -1e30f, l0 = 0.f, l1 = 0.f;
    float oacc[8][4];
#pragma unroll
    for (int nt = 0; nt < 8; nt++)
#pragma unroll
        for (int e = 0; e < 4; e++) oacc[nt][e] = 0.f;

    for (int kt = 0; kt <= qt; kt++) {
        const int k0 = kt * 64;
        __syncthreads();
        for (int i = tid; i < 64 * 8; i += 128) {
            const int r = i >> 3, c = (i & 7) * 8;
            *(uint4*)(Ks + r * KROW + c) =
                *(const uint4*)(K + base + (size_t)(k0 + r) * Dc + c);
            *(uint4*)(Vs + r * KROW + c) =
                *(const uint4*)(V + base + (size_t)(k0 + r) * Dc + c);
        }
        if (tid < 64) km[tid] = mask[b * Sc + k0 + tid];
        __syncthreads();

        float sc[8][4];
#pragma unroll
        for (int nt = 0; nt < 8; nt++) {
            sc[nt][0] = sc[nt][1] = sc[nt][2] = sc[nt][3] = 0.f;
#pragma unroll
            for (int ks = 0; ks < 4; ks++) {
                uint32_t b0, b1;
                const uint32_t addr = ksb
                    + (uint32_t)(((nt * 8 + (l16 & 7)) * KROW
                                  + ks * 16 + (l16 >> 3) * 8) * 2);
                LDSM_X2(b0, b1, addr);
                mma_f16_16x8x16(sc[nt][0], sc[nt][1], sc[nt][2], sc[nt][3],
                                qf[ks][0], qf[ks][1], qf[ks][2], qf[ks][3], b0, b1);
            }
        }
        float mt0 = -1e30f, mt1 = -1e30f;
#pragma unroll
        for (int nt = 0; nt < 8; nt++) {
            const int kk0 = nt * 8 + 2 * qcol, kk1 = kk0 + 1;
            const int msk0 = km[kk0], msk1 = km[kk1];
            if ((k0 + kk0) > qg0 || msk0 == 0) sc[nt][0] = -1e30f;
            if ((k0 + kk1) > qg0 || msk1 == 0) sc[nt][1] = -1e30f;
            if ((k0 + kk0) > qg1 || msk0 == 0) sc[nt][2] = -1e30f;
            if ((k0 + kk1) > qg1 || msk1 == 0) sc[nt][3] = -1e30f;
            mt0 = fmaxf(mt0, fmaxf(sc[nt][0], sc[nt][1]));
            mt1 = fmaxf(mt1, fmaxf(sc[nt][2], sc[nt][3]));
        }
        mt0 = fmaxf(mt0, __shfl_xor_sync(0xffffffffu, mt0, 1));
        mt0 = fmaxf(mt0, __shfl_xor_sync(0xffffffffu, mt0, 2));
        mt1 = fmaxf(mt1, __shfl_xor_sync(0xffffffffu, mt1, 1));
        mt1 = fmaxf(mt1, __shfl_xor_sync(0xffffffffu, mt1, 2));
        const float mn0 = fmaxf(m0, mt0), mn1 = fmaxf(m1, mt1);
        const float sc0 = __expf(m0 - mn0), sc1 = __expf(m1 - mn1);
        float lt0 = 0.f, lt1 = 0.f;
#pragma unroll
        for (int nt = 0; nt < 8; nt++) {
            sc[nt][0] = __expf(sc[nt][0] - mn0);
            sc[nt][1] = __expf(sc[nt][1] - mn0);
            sc[nt][2] = __expf(sc[nt][2] - mn1);
            sc[nt][3] = __expf(sc[nt][3] - mn1);
            lt0 += sc[nt][0] + sc[nt][1];
            lt1 += sc[nt][2] + sc[nt][3];
        }
        lt0 += __shfl_xor_sync(0xffffffffu, lt0, 1);
        lt0 += __shfl_xor_sync(0xffffffffu, lt0, 2);
        lt1 += __shfl_xor_sync(0xffffffffu, lt1, 1);
        lt1 += __shfl_xor_sync(0xffffffffu, lt1, 2);
        l0 = l0 * sc0 + lt0; m0 = mn0;
        l1 = l1 * sc1 + lt1; m1 = mn1;
#pragma unroll
        for (int nt = 0; nt < 8; nt++) {
            oacc[nt][0] *= sc0; oacc[nt][1] *= sc0;
            oacc[nt][2] *= sc1; oacc[nt][3] *= sc1;
        }

        uint32_t pf[4][4];
#pragma unroll
        for (int ks = 0; ks < 4; ks++) {
            pf[ks][0] = pack_h2(sc[2 * ks][0],     sc[2 * ks][1]);
            pf[ks][1] = pack_h2(sc[2 * ks][2],     sc[2 * ks][3]);
            pf[ks][2] = pack_h2(sc[2 * ks + 1][0], sc[2 * ks + 1][1]);
            pf[ks][3] = pack_h2(sc[2 * ks + 1][2], sc[2 * ks + 1][3]);
        }
#pragma unroll
        for (int nt = 0; nt < 8; nt++) {
#pragma unroll
            for (int ks = 0; ks < 4; ks++) {
                uint32_t b0, b1;
                const uint32_t addr = vsb
                    + (uint32_t)(((ks * 16 + l16) * KROW + nt * 8) * 2);
                LDSM_X2T(b0, b1, addr);
                mma_f16_16x8x16(oacc[nt][0], oacc[nt][1], oacc[nt][2], oacc[nt][3],
                                pf[ks][0], pf[ks][1], pf[ks][2], pf[ks][3], b0, b1);
            }
        }
    }

    const float inv0 = (mq0 != 0) ? (1.0f / l0) : 0.f;
    const float inv1 = (mq1 != 0) ? (1.0f / l1) : 0.f;
    __half* o0 = O + base + (size_t)qg0 * Dc;
    __half* o1 = O + base + (size_t)qg1 * Dc;
#pragma unroll
    for (int nt = 0; nt < 8; nt++) {
        const int cc = nt * 8 + 2 * qcol;
        __half2 h0 = __floats2half2_rn(oacc[nt][0] * inv0, oacc[nt][1] * inv0);
        __half2 h1 = __floats2half2_rn(oacc[nt][2] * inv1, oacc[nt][3] * inv1);
        *(__half2*)(o0 + cc) = h0;
        *(__half2*)(o1 + cc) = h1;
    }
}

// ---------------- layernorm (vectorized) ----------
__device__ __forceinline__ float block_sum(float v, float* red) {
#pragma unroll
    for (int o = 16; o > 0; o >>= 1) v += __shfl_xor_sync(0xffffffffu, v, o);
    const int lane = threadIdx.x & 31, w = threadIdx.x >> 5;
    __syncthreads();
    if (lane == 0) red[w] = v;
    __syncthreads();
    float s = 0.f;
#pragma unroll
    for (int i = 0; i < 8; i++) s += red[i];
    return s;
}

__global__ void __launch_bounds__(256) ln12_kernel(
    const float* __restrict__ x, const __half* __restrict__ o,
    const float* __restrict__ cond,
    const float* __restrict__ g1, const float* __restrict__ b1,
    const float* __restrict__ g2, const float* __restrict__ b2,
    __half* __restrict__ out2h)
{
    __shared__ float red[8];
    const int row = blockIdx.x;
    const int bb  = row >> 10;
    const int d0  = threadIdx.x * 4;
    float t[4];
    {
        float4 xv = *(const float4*)(x + (size_t)row * Dc + d0);
        uint2  ov = *(const uint2*)(o + (size_t)row * Dc + d0);
        float2 o0 = __half22float2(*(__half2*)&ov.x);
        float2 o1 = __half22float2(*(__half2*)&ov.y);
        t[0] = xv.x + o0.x; t[1] = xv.y + o0.y;
        t[2] = xv.z + o1.x; t[3] = xv.w + o1.y;
    }
    float s = t[0] + t[1] + t[2] + t[3];
    float mu = block_sum(s, red) * (1.f / 1024.f);
    float vs = 0.f;
#pragma unroll
    for (int k = 0; k < 4; k++) { float dv = t[k] - mu; vs += dv * dv; }
    float var = block_sum(vs, red) * (1.f / 1024.f);
    float inv = rsqrtf(var + 1e-3f);
    {
        float4 gv = *(const float4*)(g1 + d0);
        float4 bv = *(const float4*)(b1 + d0);
        float4 cv = *(const float4*)(cond + (size_t)bb * Dc + d0);
        t[0] = (t[0] - mu) * inv * gv.x + bv.x + cv.x;
        t[1] = (t[1] - mu) * inv * gv.y + bv.y + cv.y;
        t[2] = (t[2] - mu) * inv * gv.z + bv.z + cv.z;
        t[3] = (t[3] - mu) * inv * gv.w + bv.w + cv.w;
    }
    s = t[0] + t[1] + t[2] + t[3];
    mu = block_sum(s, red) * (1.f / 1024.f);
    vs = 0.f;
#pragma unroll
    for (int k = 0; k < 4; k++) { float dv = t[k] - mu; vs += dv * dv; }
    var = block_sum(vs, red) * (1.f / 1024.f);
    inv = rsqrtf(var + 1e-3f);
    {
        float4 gv = *(const float4*)(g2 + d0);
        float4 bv = *(const float4*)(b2 + d0);
        float y0 = (t[0] - mu) * inv * gv.x + bv.x;
        float y1 = (t[1] - mu) * inv * gv.y + bv.y;
        float y2 = (t[2] - mu) * inv * gv.z + bv.z;
        float y3 = (t[3] - mu) * inv * gv.w + bv.w;
        __half2 h0 = __floats2half2_rn(y0, y1);
        __half2 h1 = __floats2half2_rn(y2, y3);
        *(uint2*)(out2h + (size_t)row * Dc + d0) =
            make_uint2(*(uint32_t*)&h0, *(uint32_t*)&h1);
    }
}

// out = LN3(out2h + Fh)  (both inputs fp16)
__global__ void __launch_bounds__(256) ln3_kernel(
    const __half* __restrict__ a, const __half* __restrict__ f,
    const float* __restrict__ g3, const float* __restrict__ b3,
    float* __restrict__ out)
{
    __shared__ float red[8];
    const int row = blockIdx.x;
    const int d0  = threadIdx.x * 4;
    float t[4];
    {
        uint2 av = *(const uint2*)(a + (size_t)row * Dc + d0);
        uint2 fv = *(const uint2*)(f + (size_t)row * Dc + d0);
        float2 a0 = __half22float2(*(__half2*)&av.x);
        float2 a1 = __half22float2(*(__half2*)&av.y);
        float2 f0 = __half22float2(*(__half2*)&fv.x);
        float2 f1 = __half22float2(*(__half2*)&fv.y);
        t[0] = a0.x + f0.x; t[1] = a0.y + f0.y;
        t[2] = a1.x + f1.x; t[3] = a1.y + f1.y;
    }
    float s = t[0] + t[1] + t[2] + t[3];
    float mu = block_sum(s, red) * (1.f / 1024.f);
    float vs = 0.f;
#pragma unroll
    for (int k = 0; k < 4; k++) { float dv = t[k] - mu; vs += dv * dv; }
    float var = block_sum(vs, red) * (1.f / 1024.f);
    float inv = rsqrtf(var + 1e-3f);
    {
        float4 gv = *(const float4*)(g3 + d0);
        float4 bv = *(const float4*)(b3 + d0);
        float4 ov;
        ov.x = (t[0] - mu) * inv * gv.x + bv.x;
        ov.y = (t[1] - mu) * inv * gv.y + bv.y;
        ov.z = (t[2] - mu) * inv * gv.z + bv.z;
        ov.w = (t[3] - mu) * inv * gv.w + bv.w;
        *(float4*)(out + (size_t)row * Dc + d0) = ov;
    }
}

// ---------------- launch ----------------
extern "C" void kernel_launch(void* const* d_in, const int* in_sizes, int n_in,
                              void* d_out, int out_size) {
    const float* x    = (const float*)d_in[0];
    const float* z    = (const float*)d_in[1];
    const float* cond = (const float*)d_in[2];
    const int*   xm   = (const int*)  d_in[3];
    const float* WQ   = (const float*)d_in[4];
    const float* WK   = (const float*)d_in[5];
    const float* WV   = (const float*)d_in[6];
    const float* W1   = (const float*)d_in[7];
    const float* b1   = (const float*)d_in[8];
    const float* W2   = (const float*)d_in[9];
    const float* b2   = (const float*)d_in[10];
    const float* g1   = (const float*)d_in[11];
    const float* be1  = (const float*)d_in[12];
    const float* g2   = (const float*)d_in[13];
    const float* be2  = (const float*)d_in[14];
    const float* g3   = (const float*)d_in[15];
    const float* be3  = (const float*)d_in[16];
    float* out = (float*)d_out;

    float *pZW1;
    __half *pFh, *pOh, *pQh, *pKh, *pVh, *pxh, *pO2h, *pHh;
    __half *pWQh, *pWKh, *pWVh, *pW1h, *pW2h;
    cudaGetSymbolAddress((void**)&pZW1, g_ZW1);
    cudaGetSymbolAddress((void**)&pFh,  g_Fh);
    cudaGetSymbolAddress((void**)&pOh,  g_Oh);
    cudaGetSymbolAddress((void**)&pQh,  g_Qh);
    cudaGetSymbolAddress((void**)&pKh,  g_Kh);
    cudaGetSymbolAddress((void**)&pVh,  g_Vh);
    cudaGetSymbolAddress((void**)&pxh,  g_xh);
    cudaGetSymbolAddress((void**)&pO2h, g_O2h);
    cudaGetSymbolAddress((void**)&pHh,  g_Hh);
    cudaGetSymbolAddress((void**)&pWQh, g_WQh);
    cudaGetSymbolAddress((void**)&pWKh, g_WKh);
    cudaGetSymbolAddress((void**)&pWVh, g_WVh);
    cudaGetSymbolAddress((void**)&pW1h, g_W1h);
    cudaGetSymbolAddress((void**)&pW2h, g_W2h);

    cudaFuncSetAttribute(mma_gemm<0>, cudaFuncAttributeMaxDynamicSharedMemorySize,
                         GEMM_SMEM_BYTES);
    cudaFuncSetAttribute(mma_gemm<1>, cudaFuncAttributeMaxDynamicSharedMemorySize,
                         GEMM_SMEM_BYTES);
    cudaFuncSetAttribute(qkv_gemm, cudaFuncAttributeMaxDynamicSharedMemorySize,
                         GEMM_SMEM_BYTES);

    // side stream for the non-critical weight conversions (event-fork pattern;
    // capture converts the record/wait pairs into graph edges)
    cudaStream_t s2;
    cudaStreamCreateWithFlags(&s2, cudaStreamNonBlocking);
    cudaEvent_t eFork, eJoin;
    cudaEventCreateWithFlags(&eFork, cudaEventDisableTiming);
    cudaEventCreateWithFlags(&eJoin, cudaEventDisableTiming);

    cudaEventRecord(eFork, 0);
    cudaStreamWaitEvent(s2, eFork, 0);
    prep_b_kernel<<<PREPB_BLOCKS, 256, 0, s2>>>(W1, W2, z, pW1h, pW2h, pZW1);
    cudaEventRecord(eJoin, s2);

    prep_a_kernel<<<PREPA_BLOCKS, 256>>>(x, WQ, WK, WV, pxh, pWQh, pWKh, pWVh);

    qkv_gemm<<<dim3(24, Mrows / 128), 256, GEMM_SMEM_BYTES>>>(
        pxh, pWQh, pWKh, pWVh, pQh, pKh, pVh);

    attn_kernel<<<dim3(Sc / 64, Hc, Bc), 128>>>(pQh, pKh, pVh, xm, pOh);

    ln12_kernel<<<Mrows, 256>>>(x, pOh, cond, g1, be1, g2, be2, pO2h);

    // join side stream before FFN1 (needs W1h + zw1)
    cudaStreamWaitEvent(0, eJoin, 0);

    mma_gemm<1><<<dim3(DFFc / 128, Mrows / 128), 256, GEMM_SMEM_BYTES>>>(
        pO2h, pW1h, b1, pZW1, pHh, DFFc, Dc, 1);
    mma_gemm<1><<<dim3(Dc / 128, Mrows / 128), 256, GEMM_SMEM_BYTES>>>(
        pHh, pW2h, b2, nullptr, pFh, Dc, DFFc, 0);

    ln3_kernel<<<Mrows, 256>>>(pO2h, pFh, g3, be3, out);

    cudaEventDestroy(eFork);
    cudaEventDestroy(eJoin);
    cudaStreamDestroy(s2);
}

// round 17
// speedup vs baseline: 1.1831x; 1.0032x over previous
#include <cuda_runtime.h>
#include <cuda_fp16.h>
#include <cstdint>

#define Bc   4
#define Sc   1024
#define Dc   1024
#define Hc   16
#define DHc  64
#define DFFc 4096
#define DLATc 256
#define Mrows (Bc * Sc)   // 4096

// ---------------- scratch (no cudaMalloc allowed) ----------------
__device__ float  g_ZW1[Bc * DFFc];
__device__ __half g_Fh [Mrows * Dc];
__device__ __half g_Oh [Mrows * Dc];
__device__ __half g_Qh [Mrows * Dc];
__device__ __half g_Kh [Mrows * Dc];
__device__ __half g_Vh [Mrows * Dc];
__device__ __half g_xh [Mrows * Dc];
__device__ __half g_O2h[Mrows * Dc];
__device__ __half g_Hh [Mrows * DFFc];
__device__ __half g_WQh[Dc * Dc];
__device__ __half g_WKh[Dc * Dc];
__device__ __half g_WVh[Dc * Dc];
__device__ __half g_W1h[Dc * DFFc];     // first 1024 rows of W1 only
__device__ __half g_W2h[DFFc * Dc];

// ---------------- PTX helpers (base ISA only) ----------------
__device__ __forceinline__ void mma_f16_16x8x16(
    float& c0, float& c1, float& c2, float& c3,
    uint32_t a0, uint32_t a1, uint32_t a2, uint32_t a3,
    uint32_t b0, uint32_t b1)
{
    asm("mma.sync.aligned.m16n8k16.row.col.f32.f16.f16.f32 "
        "{%0,%1,%2,%3}, {%4,%5,%6,%7}, {%8,%9}, {%0,%1,%2,%3};"
        : "+f"(c0), "+f"(c1), "+f"(c2), "+f"(c3)
        : "r"(a0), "r"(a1), "r"(a2), "r"(a3), "r"(b0), "r"(b1));
}
#define LDSM_X4(r0, r1, r2, r3, addr) \
    asm volatile("ldmatrix.sync.aligned.m8n8.x4.shared.b16 {%0,%1,%2,%3}, [%4];" \
        : "=r"(r0), "=r"(r1), "=r"(r2), "=r"(r3) : "r"(addr))
#define LDSM_X4T(r0, r1, r2, r3, addr) \
    asm volatile("ldmatrix.sync.aligned.m8n8.x4.trans.shared.b16 {%0,%1,%2,%3}, [%4];" \
        : "=r"(r0), "=r"(r1), "=r"(r2), "=r"(r3) : "r"(addr))
#define LDSM_X2(r0, r1, addr) \
    asm volatile("ldmatrix.sync.aligned.m8n8.x2.shared.b16 {%0,%1}, [%2];" \
        : "=r"(r0), "=r"(r1) : "r"(addr))
#define LDSM_X2T(r0, r1, addr) \
    asm volatile("ldmatrix.sync.aligned.m8n8.x2.trans.shared.b16 {%0,%1}, [%2];" \
        : "=r"(r0), "=r"(r1) : "r"(addr))
__device__ __forceinline__ uint32_t smem_to_u32(const void* p) {
    uint32_t a;
    asm("{ .reg .u64 t; cvta.to.shared.u64 t, %1; cvt.u32.u64 %0, t; }" : "=r"(a) : "l"(p));
    return a;
}
__device__ __forceinline__ uint32_t hmul2b(uint32_t a, uint32_t b) {
    __half2 r = __hmul2(*(__half2*)&a, *(__half2*)&b);
    return *(uint32_t*)&r;
}
__device__ __forceinline__ uint32_t pack_h2(float a, float b) {
    __half2 h = __floats2half2_rn(a, b);
    return *(uint32_t*)&h;
}
__device__ __forceinline__ float ex2f(float x) {
    float r;
    asm("ex2.approx.f32 %0, %1;" : "=f"(r) : "f"(x));
    return r;
}
#define CP_ASYNC16(dst, src) \
    asm volatile("cp.async.cg.shared.global [%0], [%1], 16;" :: "r"(dst), "l"(src))
#define CP_COMMIT() asm volatile("cp.async.commit_group;" ::: "memory")
#define CP_WAIT1()  asm volatile("cp.async.wait_group 1;" ::: "memory")
#define CP_WAIT0()  asm volatile("cp.async.wait_group 0;" ::: "memory")

// ---------------- prep A (critical path): x, WQ, WK, WV -> fp16 -------------
#define PREPA_BLOCKS 3584
__global__ void __launch_bounds__(256) prep_a_kernel(
    const float* __restrict__ x,  const float* __restrict__ WQ,
    const float* __restrict__ WK, const float* __restrict__ WV,
    __half* __restrict__ xh,  __half* __restrict__ WQh,
    __half* __restrict__ WKh, __half* __restrict__ WVh)
{
    int g = blockIdx.x * 256 + threadIdx.x;
    const float* s; __half* d;
    if      (g < 524288) { s = x;  d = xh;  }
    else if (g < 655360) { s = WQ; d = WQh; g -= 524288; }
    else if (g < 786432) { s = WK; d = WKh; g -= 655360; }
    else                 { s = WV; d = WVh; g -= 786432; }
    const int i = g * 8;
    float4 v0 = *(const float4*)(s + i);
    float4 v1 = *(const float4*)(s + i + 4);
    __half2 h0 = __floats2half2_rn(v0.x, v0.y);
    __half2 h1 = __floats2half2_rn(v0.z, v0.w);
    __half2 h2 = __floats2half2_rn(v1.x, v1.y);
    __half2 h3 = __floats2half2_rn(v1.z, v1.w);
    *(uint4*)(d + i) = make_uint4(*(uint32_t*)&h0, *(uint32_t*)&h1,
                                  *(uint32_t*)&h2, *(uint32_t*)&h3);
}

// ---------------- prep B (side stream): W1, W2 -> fp16 + zw1 ----------------
#define PREPB_CVT_BLOCKS 4096
#define PREPB_BLOCKS (PREPB_CVT_BLOCKS + 16)
__global__ void __launch_bounds__(256) prep_b_kernel(
    const float* __restrict__ W1, const float* __restrict__ W2,
    const float* __restrict__ z,
    __half* __restrict__ W1h, __half* __restrict__ W2h,
    float* __restrict__ zw1)
{
    const int bid = blockIdx.x;
    if (bid < PREPB_CVT_BLOCKS) {
        int g = bid * 256 + threadIdx.x;
        const float* s; __half* d;
        if (g < 524288) { s = W1; d = W1h; }
        else            { s = W2; d = W2h; g -= 524288; }
        const int i = g * 8;
        float4 v0 = *(const float4*)(s + i);
        float4 v1 = *(const float4*)(s + i + 4);
        __half2 h0 = __floats2half2_rn(v0.x, v0.y);
        __half2 h1 = __floats2half2_rn(v0.z, v0.w);
        __half2 h2 = __floats2half2_rn(v1.x, v1.y);
        __half2 h3 = __floats2half2_rn(v1.z, v1.w);
        *(uint4*)(d + i) = make_uint4(*(uint32_t*)&h0, *(uint32_t*)&h1,
                                      *(uint32_t*)&h2, *(uint32_t*)&h3);
    } else {
        const int n = (bid - PREPB_CVT_BLOCKS) * 256 + threadIdx.x;  // 0..4095
        float a0 = 0.f, a1 = 0.f, a2 = 0.f, a3 = 0.f;
#pragma unroll 8
        for (int k = 0; k < DLATc; k++) {
            const float w = W1[(size_t)(Dc + k) * DFFc + n];
            a0 += z[k] * w;
            a1 += z[DLATc + k] * w;
            a2 += z[2 * DLATc + k] * w;
            a3 += z[3 * DLATc + k] * w;
        }
        zw1[n] = a0;
        zw1[DFFc + n] = a1;
        zw1[2 * DFFc + n] = a2;
        zw1[3 * DFFc + n] = a3;
    }
}

// ---------------- fp16 mma.sync GEMM (unchanged) ----------------
#define AROW_B 144
#define BROW_B 272
#define A_BYTES (128 * AROW_B)
#define B_BYTES (64 * BROW_B)
#define BUF_BYTES (A_BYTES + B_BYTES)
#define GEMM_SMEM_BYTES (2 * BUF_BYTES)   // 71680

template<int OUTHALF>
__device__ __forceinline__ void gemm_body(
    char* smem, const __half* __restrict__ A,
    const __half* __restrict__ W, const float* __restrict__ bias,
    const float* __restrict__ zbias,
    void* __restrict__ Cv, int N, int K, int relu, int row0, int col0)
{
    const uint32_t sb = smem_to_u32(smem);
    const int tid  = threadIdx.x;
    const int wid  = tid >> 5, lane = tid & 31;
    const int wm   = wid >> 2, wn = wid & 3;
    const int qrow = lane >> 2, qcol = lane & 3;
    const int l16  = lane & 15, lhi = lane >> 4;
    const int mgrp = lane >> 3;

    float acc[4][4][4];
#pragma unroll
    for (int i = 0; i < 4; i++)
#pragma unroll
        for (int j = 0; j < 4; j++)
#pragma unroll
            for (int r = 0; r < 4; r++) acc[i][j][r] = 0.f;

    const int NC = K / 64;

#define LOAD_CHUNK(c, s) do {                                                        \
    const int _k0 = (c) * 64;                                                        \
    const uint32_t _ab = sb + (uint32_t)((s) * BUF_BYTES);                           \
    const uint32_t _bb = _ab + A_BYTES;                                              \
    _Pragma("unroll")                                                                \
    for (int _u = tid; _u < 1024; _u += 256) {                                       \
        {                                                                            \
            const int _r = _u >> 3, _sg = _u & 7;                                    \
            const __half* _as = A + (size_t)(row0 + _r) * K + _k0 + _sg * 8;         \
            CP_ASYNC16(_ab + (uint32_t)(_r * AROW_B + _sg * 16), _as);               \
        }                                                                            \
        {                                                                            \
            const int _r = _u >> 4, _sg = _u & 15;                                   \
            const __half* _bs = W + (size_t)(_k0 + _r) * N + col0 + _sg * 8;         \
            CP_ASYNC16(_bb + (uint32_t)(_r * BROW_B + _sg * 16), _bs);               \
        }                                                                            \
    }                                                                                \
    CP_COMMIT();                                                                     \
} while (0)

    LOAD_CHUNK(0, 0);
    for (int c = 0; c < NC; c++) {
        const int s = c & 1;
        if (c + 1 < NC) { LOAD_CHUNK(c + 1, s ^ 1); CP_WAIT1(); }
        else            { CP_WAIT0(); }
        __syncthreads();

        const uint32_t ab = sb + (uint32_t)(s * BUF_BYTES);
        const uint32_t bb = ab + A_BYTES;
#pragma unroll
        for (int ks = 0; ks < 4; ks++) {
            const int k = ks * 16;
            uint32_t af[4][4];
#pragma unroll
            for (int mt = 0; mt < 4; mt++) {
                const uint32_t addr = ab
                    + (uint32_t)((wm * 64 + mt * 16 + l16) * AROW_B)
                    + (uint32_t)((k + lhi * 8) * 2);
                LDSM_X4(af[mt][0], af[mt][1], af[mt][2], af[mt][3], addr);
            }
            uint32_t bf[4][2];
#pragma unroll
            for (int ntp = 0; ntp < 2; ntp++) {
                const int row = k + (lane & 7) + (mgrp & 1) * 8;
                const int col = wn * 32 + ntp * 16 + (mgrp >> 1) * 8;
                const uint32_t addr = bb + (uint32_t)(row * BROW_B + col * 2);
                LDSM_X4T(bf[2 * ntp][0], bf[2 * ntp][1],
                         bf[2 * ntp + 1][0], bf[2 * ntp + 1][1], addr);
            }
#pragma unroll
            for (int mt = 0; mt < 4; mt++)
#pragma unroll
                for (int nt = 0; nt < 4; nt++)
                    mma_f16_16x8x16(acc[mt][nt][0], acc[mt][nt][1],
                                    acc[mt][nt][2], acc[mt][nt][3],
                                    af[mt][0], af[mt][1], af[mt][2], af[mt][3],
                                    bf[nt][0], bf[nt][1]);
        }
        __syncthreads();
    }

    const float* zb = zbias ? (zbias + (size_t)(row0 >> 10) * N) : nullptr;
#pragma unroll
    for (int mt = 0; mt < 4; mt++) {
        const int r = row0 + wm * 64 + mt * 16 + qrow;
#pragma unroll
        for (int nt = 0; nt < 4; nt++) {
            const int cc = col0 + wn * 32 + nt * 8 + 2 * qcol;
            float2 v0, v1;
            v0.x = acc[mt][nt][0]; v0.y = acc[mt][nt][1];
            v1.x = acc[mt][nt][2]; v1.y = acc[mt][nt][3];
            if (bias) {
                float bx = bias[cc], by = bias[cc + 1];
                if (zb) { bx += zb[cc]; by += zb[cc + 1]; }
                v0.x += bx; v0.y += by; v1.x += bx; v1.y += by;
            }
            if (relu) {
                v0.x = fmaxf(v0.x, 0.f); v0.y = fmaxf(v0.y, 0.f);
                v1.x = fmaxf(v1.x, 0.f); v1.y = fmaxf(v1.y, 0.f);
            }
            if (OUTHALF) {
                __half* Ch = (__half*)Cv;
                __half2 h0 = __floats2half2_rn(v0.x, v0.y);
                __half2 h1 = __floats2half2_rn(v1.x, v1.y);
                *(__half2*)(Ch + (size_t)r * N + cc)       = h0;
                *(__half2*)(Ch + (size_t)(r + 8) * N + cc) = h1;
            } else {
                float* C = (float*)Cv;
                *(float2*)(C + (size_t)r * N + cc)       = v0;
                *(float2*)(C + (size_t)(r + 8) * N + cc) = v1;
            }
        }
    }
#undef LOAD_CHUNK
}

template<int OUTHALF>
__global__ void __launch_bounds__(256, 2) mma_gemm(
    const __half* __restrict__ A, const __half* __restrict__ W,
    const float* __restrict__ bias, const float* __restrict__ zbias,
    void* __restrict__ C, int N, int K, int relu)
{
    extern __shared__ char smem[];
    gemm_body<OUTHALF>(smem, A, W, bias, zbias, C, N, K, relu,
                       blockIdx.y * 128, blockIdx.x * 128);
}

__global__ void __launch_bounds__(256, 2) qkv_gemm(
    const __half* __restrict__ xh,
    const __half* __restrict__ WQ, const __half* __restrict__ WK,
    const __half* __restrict__ WV,
    __half* __restrict__ Q, __half* __restrict__ K, __half* __restrict__ V)
{
    extern __shared__ char smem[];
    const int sel  = blockIdx.x >> 3;
    const int col0 = (blockIdx.x & 7) << 7;
    const __half* W = (sel == 0) ? WQ : (sel == 1) ? WK : WV;
    __half*       C = (sel == 0) ? Q  : (sel == 1) ? K  : V;
    gemm_body<1>(smem, xh, W, nullptr, nullptr, C, Dc, Dc, 0,
                 blockIdx.y * 128, col0);
}

// ---------------- fp16 flash attention (log2-softmax, additive mask bias) ---
#define KROW 72
__global__ void __launch_bounds__(128, 4) attn_kernel(
    const __half* __restrict__ Q, const __half* __restrict__ K,
    const __half* __restrict__ V, const int* __restrict__ mask,
    __half* __restrict__ O)
{
    __shared__ __half Ks[64 * KROW];
    __shared__ __half Vs[64 * KROW];
    __shared__ float  kmb[64];
    const int qt = gridDim.x - 1 - blockIdx.x;   // LPT: longest first
    const int h = blockIdx.y, b = blockIdx.z;
    const int q0 = qt * 64;
    const int tid = threadIdx.x;
    const int w = tid >> 5, lane = tid & 31;
    const int qrow = lane >> 2, qcol = lane & 3;
    const int l16 = lane & 15, lhi = lane >> 4;
    const size_t base = ((size_t)b * Sc) * Dc + (size_t)h * DHc;
    const uint32_t ksb = smem_to_u32(Ks);
    const uint32_t vsb = smem_to_u32(Vs);

    for (int i = tid; i < 64 * 8; i += 128) {
        const int r = i >> 3, c = (i & 7) * 8;
        *(uint4*)(Ks + r * KROW + c) =
            *(const uint4*)(Q + base + (size_t)(q0 + r) * Dc + c);
    }
    __syncthreads();
    uint32_t qf[4][4];
    {
        // scale = (1/8) * log2(e): scores land directly in log2 domain
        const float QS = 0.125f * 1.44269504f;
        const uint32_t s2 = pack_h2(QS, QS);
#pragma unroll
        for (int ks = 0; ks < 4; ks++) {
            const uint32_t addr = ksb
                + (uint32_t)(((w * 16 + l16) * KROW + ks * 16 + lhi * 8) * 2);
            LDSM_X4(qf[ks][0], qf[ks][1], qf[ks][2], qf[ks][3], addr);
            qf[ks][0] = hmul2b(qf[ks][0], s2);
            qf[ks][1] = hmul2b(qf[ks][1], s2);
            qf[ks][2] = hmul2b(qf[ks][2], s2);
            qf[ks][3] = hmul2b(qf[ks][3], s2);
        }
    }
    const int qg0 = q0 + w * 16 + qrow, qg1 = qg0 + 8;
    const int mq0 = mask[b * Sc + qg0], mq1 = mask[b * Sc + qg1];

    float m0 = -1e30f, m1 = -1e30f, l0 = 0.f, l1 = 0.f;
    float oacc[8][4];
#pragma unroll
    for (int nt = 0; nt < 8; nt++)
#pragma unroll
        for (int e = 0; e < 4; e++) oacc[nt][e] = 0.f;

    for (int kt = 0; kt <= qt; kt++) {
        const int k0 = kt * 64;
        __syncthreads();
        for (int i = tid; i < 64 * 8; i += 128) {
            const int r = i >> 3, c = (i & 7) * 8;
            *(uint4*)(Ks + r * KROW + c) =
                *(const uint4*)(K + base + (size_t)(k0 + r) * Dc + c);
            *(uint4*)(Vs + r * KROW + c) =
                *(const uint4*)(V + base + (size_t)(k0 + r) * Dc + c);
        }
        if (tid < 64) kmb[tid] = mask[b * Sc + k0 + tid] ? 0.f : -1e30f;
        __syncthreads();

        float sc[8][4];
#pragma unroll
        for (int nt = 0; nt < 8; nt++) {
            sc[nt][0] = sc[nt][1] = sc[nt][2] = sc[nt][3] = 0.f;
#pragma unroll
            for (int ks = 0; ks < 4; ks++) {
                uint32_t b0, b1;
                const uint32_t addr = ksb
                    + (uint32_t)(((nt * 8 + (l16 & 7)) * KROW
                                  + ks * 16 + (l16 >> 3) * 8) * 2);
                LDSM_X2(b0, b1, addr);
                mma_f16_16x8x16(sc[nt][0], sc[nt][1], sc[nt][2], sc[nt][3],
                                qf[ks][0], qf[ks][1], qf[ks][2], qf[ks][3], b0, b1);
            }
        }
        // mask + row max. Block-uniform branch: only the diagonal tile needs
        // the per-element causal compare; others just add the padding bias.
        float mt0 = -1e30f, mt1 = -1e30f;
        if (kt == qt) {
#pragma unroll
            for (int nt = 0; nt < 8; nt++) {
                const int kk0 = nt * 8 + 2 * qcol, kk1 = kk0 + 1;
                const float bb0 = kmb[kk0], bb1 = kmb[kk1];
                sc[nt][0] += bb0; if ((k0 + kk0) > qg0) sc[nt][0] = -1e30f;
                sc[nt][1] += bb1; if ((k0 + kk1) > qg0) sc[nt][1] = -1e30f;
                sc[nt][2] += bb0; if ((k0 + kk0) > qg1) sc[nt][2] = -1e30f;
                sc[nt][3] += bb1; if ((k0 + kk1) > qg1) sc[nt][3] = -1e30f;
                mt0 = fmaxf(mt0, fmaxf(sc[nt][0], sc[nt][1]));
                mt1 = fmaxf(mt1, fmaxf(sc[nt][2], sc[nt][3]));
            }
        } else {
#pragma unroll
            for (int nt = 0; nt < 8; nt++) {
                const int kk0 = nt * 8 + 2 * qcol, kk1 = kk0 + 1;
                const float bb0 = kmb[kk0], bb1 = kmb[kk1];
                sc[nt][0] += bb0; sc[nt][1] += bb1;
                sc[nt][2] += bb0; sc[nt][3] += bb1;
                mt0 = fmaxf(mt0, fmaxf(sc[nt][0], sc[nt][1]));
                mt1 = fmaxf(mt1, fmaxf(sc[nt][2], sc[nt][3]));
            }
        }
        mt0 = fmaxf(mt0, __shfl_xor_sync(0xffffffffu, mt0, 1));
        mt0 = fmaxf(mt0, __shfl_xor_sync(0xffffffffu, mt0, 2));
        mt1 = fmaxf(mt1, __shfl_xor_sync(0xffffffffu, mt1, 1));
        mt1 = fmaxf(mt1, __shfl_xor_sync(0xffffffffu, mt1, 2));
        const float mn0 = fmaxf(m0, mt0), mn1 = fmaxf(m1, mt1);
        const float sc0 = ex2f(m0 - mn0), sc1 = ex2f(m1 - mn1);
        float lt0 = 0.f, lt1 = 0.f;
#pragma unroll
        for (int nt = 0; nt < 8; nt++) {
            sc[nt][0] = ex2f(sc[nt][0] - mn0);
            sc[nt][1] = ex2f(sc[nt][1] - mn0);
            sc[nt][2] = ex2f(sc[nt][2] - mn1);
            sc[nt][3] = ex2f(sc[nt][3] - mn1);
            lt0 += sc[nt][0] + sc[nt][1];
            lt1 += sc[nt][2] + sc[nt][3];
        }
        lt0 += __shfl_xor_sync(0xffffffffu, lt0, 1);
        lt0 += __shfl_xor_sync(0xffffffffu, lt0, 2);
        lt1 += __shfl_xor_sync(0xffffffffu, lt1, 1);
        lt1 += __shfl_xor_sync(0xffffffffu, lt1, 2);
        l0 = l0 * sc0 + lt0; m0 = mn0;
        l1 = l1 * sc1 + lt1; m1 = mn1;
#pragma unroll
        for (int nt = 0; nt < 8; nt++) {
            oacc[nt][0] *= sc0; oacc[nt][1] *= sc0;
            oacc[nt][2] *= sc1; oacc[nt][3] *= sc1;
        }

        uint32_t pf[4][4];
#pragma unroll
        for (int ks = 0; ks < 4; ks++) {
            pf[ks][0] = pack_h2(sc[2 * ks][0],     sc[2 * ks][1]);
            pf[ks][1] = pack_h2(sc[2 * ks][2],     sc[2 * ks][3]);
            pf[ks][2] = pack_h2(sc[2 * ks + 1][0], sc[2 * ks + 1][1]);
            pf[ks][3] = pack_h2(sc[2 * ks + 1][2], sc[2 * ks + 1][3]);
        }
#pragma unroll
        for (int nt = 0; nt < 8; nt++) {
#pragma unroll
            for (int ks = 0; ks < 4; ks++) {
                uint32_t b0, b1;
                const uint32_t addr = vsb
                    + (uint32_t)(((ks * 16 + l16) * KROW + nt * 8) * 2);
                LDSM_X2T(b0, b1, addr);
                mma_f16_16x8x16(oacc[nt][0], oacc[nt][1], oacc[nt][2], oacc[nt][3],
                                pf[ks][0], pf[ks][1], pf[ks][2], pf[ks][3], b0, b1);
            }
        }
    }

    const float inv0 = (mq0 != 0) ? (1.0f / l0) : 0.f;
    const float inv1 = (mq1 != 0) ? (1.0f / l1) : 0.f;
    __half* o0 = O + base + (size_t)qg0 * Dc;
    __half* o1 = O + base + (size_t)qg1 * Dc;
#pragma unroll
    for (int nt = 0; nt < 8; nt++) {
        const int cc = nt * 8 + 2 * qcol;
        __half2 h0 = __floats2half2_rn(oacc[nt][0] * inv0, oacc[nt][1] * inv0);
        __half2 h1 = __floats2half2_rn(oacc[nt][2] * inv1, oacc[nt][3] * inv1);
        *(__half2*)(o0 + cc) = h0;
        *(__half2*)(o1 + cc) = h1;
    }
}

// ---------------- layernorm (single-pass sum/sumsq statistics) ----------
__device__ __forceinline__ void block_sum2(float& a, float& b, float* red) {
#pragma unroll
    for (int o = 16; o > 0; o >>= 1) {
        a += __shfl_xor_sync(0xffffffffu, a, o);
        b += __shfl_xor_sync(0xffffffffu, b, o);
    }
    const int lane = threadIdx.x & 31, w = threadIdx.x >> 5;
    __syncthreads();
    if (lane == 0) { red[w] = a; red[8 + w] = b; }
    __syncthreads();
    a = 0.f; b = 0.f;
#pragma unroll
    for (int i = 0; i < 8; i++) { a += red[i]; b += red[8 + i]; }
}

__global__ void __launch_bounds__(256) ln12_kernel(
    const float* __restrict__ x, const __half* __restrict__ o,
    const float* __restrict__ cond,
    const float* __restrict__ g1, const float* __restrict__ b1,
    const float* __restrict__ g2, const float* __restrict__ b2,
    __half* __restrict__ out2h)
{
    __shared__ float red[16];
    const int row = blockIdx.x;
    const int bb  = row >> 10;
    const int d0  = threadIdx.x * 4;
    float t[4];
    {
        float4 xv = *(const float4*)(x + (size_t)row * Dc + d0);
        uint2  ov = *(const uint2*)(o + (size_t)row * Dc + d0);
        float2 o0 = __half22float2(*(__half2*)&ov.x);
        float2 o1 = __half22float2(*(__half2*)&ov.y);
        t[0] = xv.x + o0.x; t[1] = xv.y + o0.y;
        t[2] = xv.z + o1.x; t[3] = xv.w + o1.y;
    }
    float s = t[0] + t[1] + t[2] + t[3];
    float q = t[0]*t[0] + t[1]*t[1] + t[2]*t[2] + t[3]*t[3];
    block_sum2(s, q, red);
    float mu = s * (1.f / 1024.f);
    float inv = rsqrtf(q * (1.f / 1024.f) - mu * mu + 1e-3f);
    {
        float4 gv = *(const float4*)(g1 + d0);
        float4 bv = *(const float4*)(b1 + d0);
        float4 cv = *(const float4*)(cond + (size_t)bb * Dc + d0);
        t[0] = (t[0] - mu) * inv * gv.x + bv.x + cv.x;
        t[1] = (t[1] - mu) * inv * gv.y + bv.y + cv.y;
        t[2] = (t[2] - mu) * inv * gv.z + bv.z + cv.z;
        t[3] = (t[3] - mu) * inv * gv.w + bv.w + cv.w;
    }
    s = t[0] + t[1] + t[2] + t[3];
    q = t[0]*t[0] + t[1]*t[1] + t[2]*t[2] + t[3]*t[3];
    block_sum2(s, q, red);
    mu = s * (1.f / 1024.f);
    inv = rsqrtf(q * (1.f / 1024.f) - mu * mu + 1e-3f);
    {
        float4 gv = *(const float4*)(g2 + d0);
        float4 bv = *(const float4*)(b2 + d0);
        float y0 = (t[0] - mu) * inv * gv.x + bv.x;
        float y1 = (t[1] - mu) * inv * gv.y + bv.y;
        float y2 = (t[2] - mu) * inv * gv.z + bv.z;
        float y3 = (t[3] - mu) * inv * gv.w + bv.w;
        __half2 h0 = __floats2half2_rn(y0, y1);
        __half2 h1 = __floats2half2_rn(y2, y3);
        *(uint2*)(out2h + (size_t)row * Dc + d0) =
            make_uint2(*(uint32_t*)&h0, *(uint32_t*)&h1);
    }
}

__global__ void __launch_bounds__(256) ln3_kernel(
    const __half* __restrict__ a, const __half* __restrict__ f,
    const float* __restrict__ g3, const float* __restrict__ b3,
    float* __restrict__ out)
{
    __shared__ float red[16];
    const int row = blockIdx.x;
    const int d0  = threadIdx.x * 4;
    float t[4];
    {
        uint2 av = *(const uint2*)(a + (size_t)row * Dc + d0);
        uint2 fv = *(const uint2*)(f + (size_t)row * Dc + d0);
        float2 a0 = __half22float2(*(__half2*)&av.x);
        float2 a1 = __half22float2(*(__half2*)&av.y);
        float2 f0 = __half22float2(*(__half2*)&fv.x);
        float2 f1 = __half22float2(*(__half2*)&fv.y);
        t[0] = a0.x + f0.x; t[1] = a0.y + f0.y;
        t[2] = a1.x + f1.x; t[3] = a1.y + f1.y;
    }
    float s = t[0] + t[1] + t[2] + t[3];
    float q = t[0]*t[0] + t[1]*t[1] + t[2]*t[2] + t[3]*t[3];
    block_sum2(s, q, red);
    float mu = s * (1.f / 1024.f);
    float inv = rsqrtf(q * (1.f / 1024.f) - mu * mu + 1e-3f);
    {
        float4 gv = *(const float4*)(g3 + d0);
        float4 bv = *(const float4*)(b3 + d0);
        float4 ov;
        ov.x = (t[0] - mu) * inv * gv.x + bv.x;
        ov.y = (t[1] - mu) * inv * gv.y + bv.y;
        ov.z = (t[2] - mu) * inv * gv.z + bv.z;
        ov.w = (t[3] - mu) * inv * gv.w + bv.w;
        *(float4*)(out + (size_t)row * Dc + d0) = ov;
    }
}

// ---------------- launch ----------------
extern "C" void kernel_launch(void* const* d_in, const int* in_sizes, int n_in,
                              void* d_out, int out_size) {
    const float* x    = (const float*)d_in[0];
    const float* z    = (const float*)d_in[1];
    const float* cond = (const float*)d_in[2];
    const int*   xm   = (const int*)  d_in[3];
    const float* WQ   = (const float*)d_in[4];
    const float* WK   = (const float*)d_in[5];
    const float* WV   = (const float*)d_in[6];
    const float* W1   = (const float*)d_in[7];
    const float* b1   = (const float*)d_in[8];
    const float* W2   = (const float*)d_in[9];
    const float* b2   = (const float*)d_in[10];
    const float* g1   = (const float*)d_in[11];
    const float* be1  = (const float*)d_in[12];
    const float* g2   = (const float*)d_in[13];
    const float* be2  = (const float*)d_in[14];
    const float* g3   = (const float*)d_in[15];
    const float* be3  = (const float*)d_in[16];
    float* out = (float*)d_out;

    float *pZW1;
    __half *pFh, *pOh, *pQh, *pKh, *pVh, *pxh, *pO2h, *pHh;
    __half *pWQh, *pWKh, *pWVh, *pW1h, *pW2h;
    cudaGetSymbolAddress((void**)&pZW1, g_ZW1);
    cudaGetSymbolAddress((void**)&pFh,  g_Fh);
    cudaGetSymbolAddress((void**)&pOh,  g_Oh);
    cudaGetSymbolAddress((void**)&pQh,  g_Qh);
    cudaGetSymbolAddress((void**)&pKh,  g_Kh);
    cudaGetSymbolAddress((void**)&pVh,  g_Vh);
    cudaGetSymbolAddress((void**)&pxh,  g_xh);
    cudaGetSymbolAddress((void**)&pO2h, g_O2h);
    cudaGetSymbolAddress((void**)&pHh,  g_Hh);
    cudaGetSymbolAddress((void**)&pWQh, g_WQh);
    cudaGetSymbolAddress((void**)&pWKh, g_WKh);
    cudaGetSymbolAddress((void**)&pWVh, g_WVh);
    cudaGetSymbolAddress((void**)&pW1h, g_W1h);
    cudaGetSymbolAddress((void**)&pW2h, g_W2h);

    cudaFuncSetAttribute(mma_gemm<0>, cudaFuncAttributeMaxDynamicSharedMemorySize,
                         GEMM_SMEM_BYTES);
    cudaFuncSetAttribute(mma_gemm<1>, cudaFuncAttributeMaxDynamicSharedMemorySize,
                         GEMM_SMEM_BYTES);
    cudaFuncSetAttribute(qkv_gemm, cudaFuncAttributeMaxDynamicSharedMemorySize,
                         GEMM_SMEM_BYTES);

    // side stream for the non-critical weight conversions (event-fork pattern)
    cudaStream_t s2;
    cudaStreamCreateWithFlags(&s2, cudaStreamNonBlocking);
    cudaEvent_t eFork, eJoin;
    cudaEventCreateWithFlags(&eFork, cudaEventDisableTiming);
    cudaEventCreateWithFlags(&eJoin, cudaEventDisableTiming);

    cudaEventRecord(eFork, 0);
    cudaStreamWaitEvent(s2, eFork, 0);
    prep_b_kernel<<<PREPB_BLOCKS, 256, 0, s2>>>(W1, W2, z, pW1h, pW2h, pZW1);
    cudaEventRecord(eJoin, s2);

    prep_a_kernel<<<PREPA_BLOCKS, 256>>>(x, WQ, WK, WV, pxh, pWQh, pWKh, pWVh);

    qkv_gemm<<<dim3(24, Mrows / 128), 256, GEMM_SMEM_BYTES>>>(
        pxh, pWQh, pWKh, pWVh, pQh, pKh, pVh);

    attn_kernel<<<dim3(Sc / 64, Hc, Bc), 128>>>(pQh, pKh, pVh, xm, pOh);

    ln12_kernel<<<Mrows, 256>>>(x, pOh, cond, g1, be1, g2, be2, pO2h);

    // join side stream before FFN1 (needs W1h + zw1)
    cudaStreamWaitEvent(0, eJoin, 0);

    mma_gemm<1><<<dim3(DFFc / 128, Mrows / 128), 256, GEMM_SMEM_BYTES>>>(
        pO2h, pW1h, b1, pZW1, pHh, DFFc, Dc, 1);
    mma_gemm<1><<<dim3(Dc / 128, Mrows / 128), 256, GEMM_SMEM_BYTES>>>(
        pHh, pW2h, b2, nullptr, pFh, Dc, DFFc, 0);

    ln3_kernel<<<Mrows, 256>>>(pO2h, pFh, g3, be3, out);

    cudaEventDestroy(eFork);
    cudaEventDestroy(eJoin);
    cudaStreamDestroy(s2);
}